// round 7
// baseline (speedup 1.0000x reference)
#include <cuda_runtime.h>
#include <cuda_bf16.h>
#include <cstdint>

#define B_    32
#define VLEN_ 2048
#define H_    1024
#define DIM_  1024
#define C_    32
#define KC    1088              // 1024 (value) + 32 (conv feat) + 32 zero pad
#define M_    (B_*VLEN_)        // 65536

// ---------------- scratch (device globals: no runtime allocation) ----------------
__device__ __nv_bfloat16 g_valcat[(size_t)M_*KC];    // [65536][1088] bf16  (~142 MB)
__device__ __nv_bfloat16 g_wcat[(size_t)DIM_*KC];    // [1024][1088] bf16
__device__ float g_qbias[B_*DIM_];                   // qp[b,d] + bias[d]
__device__ float g_score[M_];
__device__ float g_attn[M_];
__device__ float g_context[B_*H_];

__device__ __forceinline__ uint32_t smem_u32(const void* p){
    return (uint32_t)__cvta_generic_to_shared(p);
}

// -------- prep: A matrix = [value(bf16) | conv_feat(bf16) | 0]; also zeroes g_score --------
__global__ void build_valcat(const float* __restrict__ value,
                             const float* __restrict__ prev_attn,
                             const float* __restrict__ conv_w,
                             const float* __restrict__ conv_b) {
    int t = blockIdx.x*256 + threadIdx.x;               // one 16B chunk each
    const int CHUNKS = KC/8;                            // 136
    if (t < M_) g_score[t] = 0.f;                       // fused zero_score
    if (t >= M_*CHUNKS) return;
    int bv = t / CHUNKS, chunk = t % CHUNKS;
    __align__(16) __nv_bfloat16 o[8];
    if (chunk < 128) {
        const float4* s = reinterpret_cast<const float4*>(value + (size_t)bv*H_ + chunk*8);
        float4 x = s[0], y = s[1];
        o[0]=__float2bfloat16(x.x); o[1]=__float2bfloat16(x.y);
        o[2]=__float2bfloat16(x.z); o[3]=__float2bfloat16(x.w);
        o[4]=__float2bfloat16(y.x); o[5]=__float2bfloat16(y.y);
        o[6]=__float2bfloat16(y.z); o[7]=__float2bfloat16(y.w);
    } else if (chunk < 132) {
        int b = bv >> 11, v = bv & 2047;
        float pm = (v > 0)        ? prev_attn[b*VLEN_ + v - 1] : 0.f;
        float pc =                  prev_attn[b*VLEN_ + v];
        float pp = (v < VLEN_-1)  ? prev_attn[b*VLEN_ + v + 1] : 0.f;
        int c0 = (chunk-128)*8;
        #pragma unroll
        for (int j = 0; j < 8; j++) {
            int c = c0 + j;
            float cf = conv_w[c*3+0]*pm + conv_w[c*3+1]*pc + conv_w[c*3+2]*pp + conv_b[c];
            o[j] = __float2bfloat16(cf);
        }
    } else {
        #pragma unroll
        for (int j = 0; j < 8; j++) o[j] = __float2bfloat16(0.f);
    }
    *reinterpret_cast<uint4*>(g_valcat + (size_t)bv*KC + chunk*8) = *reinterpret_cast<uint4*>(o);
}

// ---------------- prep: B matrix = [w_v | w_loc | 0] ----------------
__global__ void build_wcat(const float* __restrict__ w_v, const float* __restrict__ w_loc) {
    int t = blockIdx.x*256 + threadIdx.x;
    const int CHUNKS = KC/8;
    if (t >= DIM_*CHUNKS) return;
    int d = t / CHUNKS, chunk = t % CHUNKS;
    __align__(16) __nv_bfloat16 o[8];
    if (chunk < 128) {
        const float* s = w_v + (size_t)d*H_ + chunk*8;
        #pragma unroll
        for (int j = 0; j < 8; j++) o[j] = __float2bfloat16(s[j]);
    } else if (chunk < 132) {
        const float* s = w_loc + (size_t)d*C_ + (chunk-128)*8;
        #pragma unroll
        for (int j = 0; j < 8; j++) o[j] = __float2bfloat16(s[j]);
    } else {
        #pragma unroll
        for (int j = 0; j < 8; j++) o[j] = __float2bfloat16(0.f);
    }
    *reinterpret_cast<uint4*>(g_wcat + (size_t)d*KC + chunk*8) = *reinterpret_cast<uint4*>(o);
}

// ---------------- prep: qbias[b,d] = query[b] . w_q[d] + bias[d] (fp32 exact) ----------------
__global__ void qbias_kernel(const float* __restrict__ query,
                             const float* __restrict__ w_q,
                             const float* __restrict__ bias) {
    int b = blockIdx.y;
    int warp = threadIdx.x >> 5, lane = threadIdx.x & 31;
    int d = blockIdx.x*8 + warp;
    const float* q = query + b*H_;
    const float* w = w_q + (size_t)d*H_;
    float acc = 0.f;
    for (int h = lane; h < H_; h += 32) acc += q[h]*w[h];
    #pragma unroll
    for (int o = 16; o; o >>= 1) acc += __shfl_xor_sync(0xffffffffu, acc, o);
    if (!lane) g_qbias[b*DIM_ + d] = acc + bias[d];
}

// ---------------- fused GEMM + tanh + score reduction (HMMA path) ----------------
// C[m,n] = sum_k A[m,k]*B[n,k] ; score[m] += sum_n tanh(C + qbias[b,n]) * w_score[n]
// BM=128, BN=128, BK=32, 8 warps (4 along M x 2 along N), warp tile 32x64.
// 4-stage cp.async pipeline, ONE __syncthreads per TWO k-steps, 2 CTAs/SM.
#define BM 128
#define BN 128
#define BK 32
#define STG 4
#define KPAD 40   // padded smem row (bf16 elems) -> conflict-free ldmatrix

#define A_STG_ELEMS (BM*KPAD)            // 5120
#define B_STG_ELEMS (BN*KPAD)            // 5120
#define SM_A_OFF 0
#define SM_B_OFF (STG*A_STG_ELEMS*2)                    // 40960
#define SM_QB_OFF (SM_B_OFF + STG*B_STG_ELEMS*2)        // 81920
#define SM_WS_OFF (SM_QB_OFF + BN*4)
#define SMEM_TOTAL_GEMM (SM_WS_OFF + BN*4)              // 82944

__device__ __forceinline__ void mma16816(float* c, const uint32_t* a, uint32_t b0, uint32_t b1) {
    asm volatile("mma.sync.aligned.m16n8k16.row.col.f32.bf16.bf16.f32 "
                 "{%0,%1,%2,%3}, {%4,%5,%6,%7}, {%8,%9}, {%0,%1,%2,%3};"
                 : "+f"(c[0]), "+f"(c[1]), "+f"(c[2]), "+f"(c[3])
                 : "r"(a[0]), "r"(a[1]), "r"(a[2]), "r"(a[3]), "r"(b0), "r"(b1));
}

__global__ __launch_bounds__(256, 2)
void gemm_score_kernel(const float* __restrict__ w_score) {
    extern __shared__ __align__(16) char sm[];
    __nv_bfloat16* As = reinterpret_cast<__nv_bfloat16*>(sm + SM_A_OFF);  // [STG][BM][KPAD]
    __nv_bfloat16* Bs = reinterpret_cast<__nv_bfloat16*>(sm + SM_B_OFF);  // [STG][BN][KPAD]
    float* qb_s = reinterpret_cast<float*>(sm + SM_QB_OFF);
    float* ws_s = reinterpret_cast<float*>(sm + SM_WS_OFF);

    const int t = threadIdx.x;
    const int warp = t >> 5, lane = t & 31;
    const int bn0 = blockIdx.x * BN;   // x fastest -> n-CTAs of one m-block co-resident
    const int bm0 = blockIdx.y * BM;
    const int batch = bm0 >> 11;       // 2048 rows per batch; BM | 2048

    if (t < BN) {
        qb_s[t] = g_qbias[batch*DIM_ + bn0 + t];
        ws_s[t] = w_score[bn0 + t];
    }

    const int lrow = t >> 2;      // 0..63
    const int lch  = t & 3;       // 16B chunk within 64B k-slab
    const __nv_bfloat16* Ag = g_valcat + (size_t)bm0*KC + lch*8;
    const __nv_bfloat16* Bg = g_wcat   + (size_t)bn0*KC + lch*8;

    const int wm = (warp >> 1) * 32;   // 4 warps along M
    const int wn = (warp & 1) * 64;    // 2 warps along N
    const int g = lane >> 3, idx = lane & 7;
    // precomputed ldmatrix row/col constants
    const int a_row0 = wm + idx + 8*(g & 1);      // + mi*16
    const int a_col0 = 8*(g >> 1);                // + kb
    const int b_row0 = wn + idx + 8*(g >> 1);     // + ni*16
    const int b_col0 = 8*(g & 1);                 // + kb

    float acc[2][8][4];
    #pragma unroll
    for (int i = 0; i < 2; i++)
        #pragma unroll
        for (int j = 0; j < 8; j++)
            #pragma unroll
            for (int k = 0; k < 4; k++) acc[i][j][k] = 0.f;

    auto load_stage = [&](int s) {
        int slot = s % STG;
        int k0 = s * BK;
        __nv_bfloat16* Ad = As + slot*A_STG_ELEMS;
        __nv_bfloat16* Bd = Bs + slot*B_STG_ELEMS;
        #pragma unroll
        for (int i = 0; i < 2; i++) {
            int r = lrow + i*64;
            uint32_t d = smem_u32(Ad + r*KPAD + lch*8);
            asm volatile("cp.async.cg.shared.global [%0], [%1], 16;\n"
                         :: "r"(d), "l"(Ag + (size_t)r*KC + k0));
            uint32_t db = smem_u32(Bd + r*KPAD + lch*8);
            asm volatile("cp.async.cg.shared.global [%0], [%1], 16;\n"
                         :: "r"(db), "l"(Bg + (size_t)r*KC + k0));
        }
        asm volatile("cp.async.commit_group;\n");
    };

    auto compute_stage = [&](int s) {
        int slot = s % STG;
        const __nv_bfloat16* Asl = As + slot*A_STG_ELEMS;
        const __nv_bfloat16* Bsl = Bs + slot*B_STG_ELEMS;
        #pragma unroll
        for (int kk = 0; kk < 2; ++kk) {
            const int kb = kk*16;
            uint32_t a[2][4];
            #pragma unroll
            for (int mi = 0; mi < 2; mi++) {
                uint32_t addr = smem_u32(Asl + (a_row0 + mi*16)*KPAD + a_col0 + kb);
                asm volatile("ldmatrix.sync.aligned.m8n8.x4.shared.b16 {%0,%1,%2,%3}, [%4];"
                             : "=r"(a[mi][0]), "=r"(a[mi][1]), "=r"(a[mi][2]), "=r"(a[mi][3])
                             : "r"(addr));
            }
            uint32_t bfrag[4][4];
            #pragma unroll
            for (int ni = 0; ni < 4; ni++) {
                uint32_t addr = smem_u32(Bsl + (b_row0 + ni*16)*KPAD + b_col0 + kb);
                asm volatile("ldmatrix.sync.aligned.m8n8.x4.shared.b16 {%0,%1,%2,%3}, [%4];"
                             : "=r"(bfrag[ni][0]), "=r"(bfrag[ni][1]), "=r"(bfrag[ni][2]), "=r"(bfrag[ni][3])
                             : "r"(addr));
            }
            #pragma unroll
            for (int mi = 0; mi < 2; mi++)
                #pragma unroll
                for (int ni = 0; ni < 4; ni++) {
                    mma16816(acc[mi][ni*2+0], a[mi], bfrag[ni][0], bfrag[ni][1]);
                    mma16816(acc[mi][ni*2+1], a[mi], bfrag[ni][2], bfrag[ni][3]);
                }
        }
    };

    const int NK = KC / BK;  // 34 (even)
    load_stage(0); load_stage(1);    // 2 groups in flight

    // pair loop: one barrier per TWO k-steps.
    // Iter j (s=2j): barrier protects slots (s+2)%4,(s+3)%4 == slots of s-2,s-1
    // (computed in iter j-1). Loads issued BEFORE the wait so DMA overlaps it.
    for (int s = 0; s < NK; s += 2) {
        __syncthreads();
        if (s + 2 < NK) {
            load_stage(s + 2);
            load_stage(s + 3);
            asm volatile("cp.async.wait_group 2;\n");   // s, s+1 landed
        } else {
            asm volatile("cp.async.wait_group 0;\n");
        }
        __syncthreads();   // all warps see s, s+1 data (wait is per-thread)
        compute_stage(s);
        compute_stage(s + 1);
    }

    // epilogue: tanh + weighted reduce over this CTA's 128 d-columns
    #pragma unroll
    for (int mi = 0; mi < 2; mi++) {
        float s0 = 0.f, s1 = 0.f;   // rows (lane>>2) and (lane>>2)+8
        #pragma unroll
        for (int j = 0; j < 8; j++) {
            int nc = wn + j*8 + 2*(lane & 3);
            float qb0 = qb_s[nc], qb1 = qb_s[nc+1];
            float w0 = ws_s[nc],  w1 = ws_s[nc+1];
            s0 += tanhf(acc[mi][j][0] + qb0)*w0 + tanhf(acc[mi][j][1] + qb1)*w1;
            s1 += tanhf(acc[mi][j][2] + qb0)*w0 + tanhf(acc[mi][j][3] + qb1)*w1;
        }
        s0 += __shfl_xor_sync(0xffffffffu, s0, 1);
        s0 += __shfl_xor_sync(0xffffffffu, s0, 2);
        s1 += __shfl_xor_sync(0xffffffffu, s1, 1);
        s1 += __shfl_xor_sync(0xffffffffu, s1, 2);
        if ((lane & 3) == 0) {
            int m0 = bm0 + wm + mi*16 + (lane >> 2);
            atomicAdd(&g_score[m0],     s0);
            atomicAdd(&g_score[m0 + 8], s1);
        }
    }
}

// ---------------- sigmoid + normalize -> attn (also zero context) ----------------
__global__ void normalize_kernel(const float* __restrict__ b_score, float* __restrict__ attn_out,
                                 int write_attn) {
    int b = blockIdx.x, t = threadIdx.x;     // 256 threads, 2048 elems
    __shared__ float red[256];
    for (int h = t; h < H_; h += 256) g_context[b*H_ + h] = 0.f;
    float bs = b_score[0];
    float sv[8];
    float local = 0.f;
    #pragma unroll
    for (int i = 0; i < 8; i++) {
        float x = g_score[b*VLEN_ + t + i*256] + bs;
        float s = 1.f / (1.f + __expf(-x));
        sv[i] = s; local += s;
    }
    red[t] = local; __syncthreads();
    #pragma unroll
    for (int o = 128; o; o >>= 1) { if (t < o) red[t] += red[t+o]; __syncthreads(); }
    float inv = 1.f / red[0];
    #pragma unroll
    for (int i = 0; i < 8; i++) {
        float a = sv[i] * inv;
        g_attn[b*VLEN_ + t + i*256] = a;
        if (write_attn) attn_out[b*VLEN_ + t + i*256] = a;
    }
}

// ---------------- context[b,h] = sum_v attn[b,v] * value[b,v,h] ----------------
__global__ void context_kernel(const float* __restrict__ value) {
    int hc = blockIdx.x, b = blockIdx.y, vs = blockIdx.z;   // (4, B, 8)
    int h = hc*256 + threadIdx.x;
    __shared__ float a_s[256];
    a_s[threadIdx.x] = g_attn[b*VLEN_ + vs*256 + threadIdx.x];
    __syncthreads();
    const float* vp = value + ((size_t)b*VLEN_ + vs*256)*H_ + h;
    float acc = 0.f;
    #pragma unroll 8
    for (int v = 0; v < 256; v++) acc += a_s[v] * vp[(size_t)v*H_];
    atomicAdd(&g_context[b*H_ + h], acc);
}

// ---------------- output[b,h] = w_out[h] . [context | query] + b_out[h] ----------------
__global__ void output_kernel(const float* __restrict__ w_out, const float* __restrict__ b_out,
                              const float* __restrict__ query, float* __restrict__ out) {
    int b = blockIdx.y;
    int warp = threadIdx.x >> 5, lane = threadIdx.x & 31;
    int h = blockIdx.x*8 + warp;
    const float* wr = w_out + (size_t)h*(2*H_);
    const float* ctx = g_context + b*H_;
    const float* q = query + b*H_;
    float acc = 0.f;
    for (int k = lane; k < H_; k += 32) acc += wr[k]*ctx[k];
    for (int k = lane; k < H_; k += 32) acc += wr[H_+k]*q[k];
    #pragma unroll
    for (int o = 16; o; o >>= 1) acc += __shfl_xor_sync(0xffffffffu, acc, o);
    if (!lane) out[b*H_ + h] = acc + b_out[h];
}

// ---------------- launch ----------------
extern "C" void kernel_launch(void* const* d_in, const int* in_sizes, int n_in,
                              void* d_out, int out_size) {
    const float* query     = (const float*)d_in[0];
    const float* value     = (const float*)d_in[1];
    const float* prev_attn = (const float*)d_in[2];
    const float* conv_w    = (const float*)d_in[3];
    const float* conv_b    = (const float*)d_in[4];
    const float* w_loc     = (const float*)d_in[5];
    const float* w_q       = (const float*)d_in[6];
    const float* w_v       = (const float*)d_in[7];
    const float* bias      = (const float*)d_in[8];
    const float* w_score   = (const float*)d_in[9];
    const float* b_score   = (const float*)d_in[10];
    const float* w_out     = (const float*)d_in[11];
    const float* b_out     = (const float*)d_in[12];
    float* out = (float*)d_out;

    (void)in_sizes; (void)n_in;

    cudaFuncSetAttribute(gemm_score_kernel,
                         cudaFuncAttributeMaxDynamicSharedMemorySize, SMEM_TOTAL_GEMM);

    build_valcat<<< (M_*(KC/8))/256, 256 >>>(value, prev_attn, conv_w, conv_b);
    build_wcat<<< (DIM_*(KC/8) + 255)/256, 256 >>>(w_v, w_loc);
    qbias_kernel<<< dim3(DIM_/8, B_), 256 >>>(query, w_q, bias);
    gemm_score_kernel<<< dim3(DIM_/BN, M_/BM), 256, SMEM_TOTAL_GEMM >>>(w_score);

    int write_attn = (out_size >= B_*H_ + M_) ? 1 : 0;   // output first, then attn
    normalize_kernel<<< B_, 256 >>>(b_score, out + B_*H_, write_attn);
    context_kernel<<< dim3(H_/256, B_, VLEN_/256), 256 >>>(value);
    output_kernel<<< dim3(H_/8, B_), 256 >>>(w_out, b_out, query, out);
}

// round 8
// speedup vs baseline: 1.1114x; 1.1114x over previous
#include <cuda_runtime.h>
#include <cuda_bf16.h>
#include <cstdint>

#define B_    32
#define VLEN_ 2048
#define H_    1024
#define DIM_  1024
#define C_    32
#define KC    1088              // 1024 (value) + 32 (conv feat) + 32 zero pad
#define M_    (B_*VLEN_)        // 65536

// ---------------- scratch (device globals: no runtime allocation) ----------------
__device__ __nv_bfloat16 g_valcat[(size_t)M_*KC];    // [65536][1088] bf16  (~142 MB)
__device__ __nv_bfloat16 g_wcat[(size_t)DIM_*KC];    // [1024][1088] bf16
__device__ float g_qbias[B_*DIM_];                   // qp[b,d] + bias[d]
__device__ float g_score[M_];
__device__ float g_attn[M_];
__device__ float g_context[B_*H_];

__device__ __forceinline__ uint32_t smem_u32(const void* p){
    return (uint32_t)__cvta_generic_to_shared(p);
}

// -------- prep: A matrix = [value(bf16) | conv_feat(bf16) | 0]; also zeroes g_score --------
__global__ void build_valcat(const float* __restrict__ value,
                             const float* __restrict__ prev_attn,
                             const float* __restrict__ conv_w,
                             const float* __restrict__ conv_b) {
    int t = blockIdx.x*256 + threadIdx.x;               // one 16B chunk each
    const int CHUNKS = KC/8;                            // 136
    if (t < M_) g_score[t] = 0.f;                       // fused zero_score
    if (t >= M_*CHUNKS) return;
    int bv = t / CHUNKS, chunk = t % CHUNKS;
    __align__(16) __nv_bfloat16 o[8];
    if (chunk < 128) {
        const float4* s = reinterpret_cast<const float4*>(value + (size_t)bv*H_ + chunk*8);
        float4 x = s[0], y = s[1];
        o[0]=__float2bfloat16(x.x); o[1]=__float2bfloat16(x.y);
        o[2]=__float2bfloat16(x.z); o[3]=__float2bfloat16(x.w);
        o[4]=__float2bfloat16(y.x); o[5]=__float2bfloat16(y.y);
        o[6]=__float2bfloat16(y.z); o[7]=__float2bfloat16(y.w);
    } else if (chunk < 132) {
        int b = bv >> 11, v = bv & 2047;
        float pm = (v > 0)        ? prev_attn[b*VLEN_ + v - 1] : 0.f;
        float pc =                  prev_attn[b*VLEN_ + v];
        float pp = (v < VLEN_-1)  ? prev_attn[b*VLEN_ + v + 1] : 0.f;
        int c0 = (chunk-128)*8;
        #pragma unroll
        for (int j = 0; j < 8; j++) {
            int c = c0 + j;
            float cf = conv_w[c*3+0]*pm + conv_w[c*3+1]*pc + conv_w[c*3+2]*pp + conv_b[c];
            o[j] = __float2bfloat16(cf);
        }
    } else {
        #pragma unroll
        for (int j = 0; j < 8; j++) o[j] = __float2bfloat16(0.f);
    }
    *reinterpret_cast<uint4*>(g_valcat + (size_t)bv*KC + chunk*8) = *reinterpret_cast<uint4*>(o);
}

// ---------------- prep: B matrix = [w_v | w_loc | 0] ----------------
__global__ void build_wcat(const float* __restrict__ w_v, const float* __restrict__ w_loc) {
    int t = blockIdx.x*256 + threadIdx.x;
    const int CHUNKS = KC/8;
    if (t >= DIM_*CHUNKS) return;
    int d = t / CHUNKS, chunk = t % CHUNKS;
    __align__(16) __nv_bfloat16 o[8];
    if (chunk < 128) {
        const float* s = w_v + (size_t)d*H_ + chunk*8;
        #pragma unroll
        for (int j = 0; j < 8; j++) o[j] = __float2bfloat16(s[j]);
    } else if (chunk < 132) {
        const float* s = w_loc + (size_t)d*C_ + (chunk-128)*8;
        #pragma unroll
        for (int j = 0; j < 8; j++) o[j] = __float2bfloat16(s[j]);
    } else {
        #pragma unroll
        for (int j = 0; j < 8; j++) o[j] = __float2bfloat16(0.f);
    }
    *reinterpret_cast<uint4*>(g_wcat + (size_t)d*KC + chunk*8) = *reinterpret_cast<uint4*>(o);
}

// ---------------- prep: qbias[b,d] = query[b] . w_q[d] + bias[d] (fp32 exact) ----------------
__global__ void qbias_kernel(const float* __restrict__ query,
                             const float* __restrict__ w_q,
                             const float* __restrict__ bias) {
    int b = blockIdx.y;
    int warp = threadIdx.x >> 5, lane = threadIdx.x & 31;
    int d = blockIdx.x*8 + warp;
    const float* q = query + b*H_;
    const float* w = w_q + (size_t)d*H_;
    float acc = 0.f;
    for (int h = lane; h < H_; h += 32) acc += q[h]*w[h];
    #pragma unroll
    for (int o = 16; o; o >>= 1) acc += __shfl_xor_sync(0xffffffffu, acc, o);
    if (!lane) g_qbias[b*DIM_ + d] = acc + bias[d];
}

// ---------------- fused GEMM + tanh + score reduction (HMMA path) ----------------
// C[m,n] = sum_k A[m,k]*B[n,k] ; score[m] += sum_n tanh(C + qbias[b,n]) * w_score[n]
// BM=128, BN=128, BK=32, 8 warps (4 along M x 2 along N), warp tile 32x64.
// 4-stage cp.async pipeline + PING-PONG REGISTER FRAGMENTS: every mma batch
// issues after the next ldmatrix batch, so LDSM latency hides under HMMA.
#define BM 128
#define BN 128
#define BK 32
#define STG 4
#define KPAD 40   // padded smem row (bf16 elems) -> conflict-free ldmatrix

#define A_STG_ELEMS (BM*KPAD)            // 5120
#define B_STG_ELEMS (BN*KPAD)            // 5120
#define SM_A_OFF 0
#define SM_B_OFF (STG*A_STG_ELEMS*2)                    // 40960
#define SM_QB_OFF (SM_B_OFF + STG*B_STG_ELEMS*2)        // 81920
#define SM_WS_OFF (SM_QB_OFF + BN*4)
#define SMEM_TOTAL_GEMM (SM_WS_OFF + BN*4)              // 82944

__device__ __forceinline__ void mma16816(float* c, const uint32_t* a, uint32_t b0, uint32_t b1) {
    asm volatile("mma.sync.aligned.m16n8k16.row.col.f32.bf16.bf16.f32 "
                 "{%0,%1,%2,%3}, {%4,%5,%6,%7}, {%8,%9}, {%0,%1,%2,%3};"
                 : "+f"(c[0]), "+f"(c[1]), "+f"(c[2]), "+f"(c[3])
                 : "r"(a[0]), "r"(a[1]), "r"(a[2]), "r"(a[3]), "r"(b0), "r"(b1));
}

__global__ __launch_bounds__(256, 2)
void gemm_score_kernel(const float* __restrict__ w_score) {
    extern __shared__ __align__(16) char sm[];
    __nv_bfloat16* As = reinterpret_cast<__nv_bfloat16*>(sm + SM_A_OFF);  // [STG][BM][KPAD]
    __nv_bfloat16* Bs = reinterpret_cast<__nv_bfloat16*>(sm + SM_B_OFF);  // [STG][BN][KPAD]
    float* qb_s = reinterpret_cast<float*>(sm + SM_QB_OFF);
    float* ws_s = reinterpret_cast<float*>(sm + SM_WS_OFF);

    const int t = threadIdx.x;
    const int warp = t >> 5, lane = t & 31;
    const int bn0 = blockIdx.x * BN;   // x fastest -> n-CTAs of one m-block co-resident
    const int bm0 = blockIdx.y * BM;
    const int batch = bm0 >> 11;       // 2048 rows per batch; BM | 2048

    if (t < BN) {
        qb_s[t] = g_qbias[batch*DIM_ + bn0 + t];
        ws_s[t] = w_score[bn0 + t];
    }

    const int lrow = t >> 2;      // 0..63
    const int lch  = t & 3;       // 16B chunk within 64B k-slab
    const __nv_bfloat16* Ag = g_valcat + (size_t)bm0*KC + lch*8;
    const __nv_bfloat16* Bg = g_wcat   + (size_t)bn0*KC + lch*8;

    const int wm = (warp >> 1) * 32;   // 4 warps along M
    const int wn = (warp & 1) * 64;    // 2 warps along N
    const int g = lane >> 3, idx = lane & 7;
    const int a_row0 = wm + idx + 8*(g & 1);      // + mi*16
    const int a_col0 = 8*(g >> 1);                // + kb
    const int b_row0 = wn + idx + 8*(g >> 1);     // + ni*16
    const int b_col0 = 8*(g & 1);                 // + kb

    float acc[2][8][4];
    #pragma unroll
    for (int i = 0; i < 2; i++)
        #pragma unroll
        for (int j = 0; j < 8; j++)
            #pragma unroll
            for (int k = 0; k < 4; k++) acc[i][j][k] = 0.f;

    auto load_stage = [&](int s) {
        int slot = s % STG;
        int k0 = s * BK;
        __nv_bfloat16* Ad = As + slot*A_STG_ELEMS;
        __nv_bfloat16* Bd = Bs + slot*B_STG_ELEMS;
        #pragma unroll
        for (int i = 0; i < 2; i++) {
            int r = lrow + i*64;
            uint32_t d = smem_u32(Ad + r*KPAD + lch*8);
            asm volatile("cp.async.cg.shared.global [%0], [%1], 16;\n"
                         :: "r"(d), "l"(Ag + (size_t)r*KC + k0));
            uint32_t db = smem_u32(Bd + r*KPAD + lch*8);
            asm volatile("cp.async.cg.shared.global [%0], [%1], 16;\n"
                         :: "r"(db), "l"(Bg + (size_t)r*KC + k0));
        }
        asm volatile("cp.async.commit_group;\n");
    };

    // load one kk-half's fragments (6 ldmatrix.x4) into caller regs
    auto ldsm_half = [&](int s, int kb, uint32_t a[2][4], uint32_t bf[4][4]) {
        const __nv_bfloat16* Asl = As + (s % STG)*A_STG_ELEMS;
        const __nv_bfloat16* Bsl = Bs + (s % STG)*B_STG_ELEMS;
        #pragma unroll
        for (int mi = 0; mi < 2; mi++) {
            uint32_t addr = smem_u32(Asl + (a_row0 + mi*16)*KPAD + a_col0 + kb);
            asm volatile("ldmatrix.sync.aligned.m8n8.x4.shared.b16 {%0,%1,%2,%3}, [%4];"
                         : "=r"(a[mi][0]), "=r"(a[mi][1]), "=r"(a[mi][2]), "=r"(a[mi][3])
                         : "r"(addr));
        }
        #pragma unroll
        for (int ni = 0; ni < 4; ni++) {
            uint32_t addr = smem_u32(Bsl + (b_row0 + ni*16)*KPAD + b_col0 + kb);
            asm volatile("ldmatrix.sync.aligned.m8n8.x4.shared.b16 {%0,%1,%2,%3}, [%4];"
                         : "=r"(bf[ni][0]), "=r"(bf[ni][1]), "=r"(bf[ni][2]), "=r"(bf[ni][3])
                         : "r"(addr));
        }
    };

    auto mma_half = [&](uint32_t a[2][4], uint32_t bf[4][4]) {
        #pragma unroll
        for (int mi = 0; mi < 2; mi++)
            #pragma unroll
            for (int ni = 0; ni < 4; ni++) {
                mma16816(acc[mi][ni*2+0], a[mi], bf[ni][0], bf[ni][1]);
                mma16816(acc[mi][ni*2+1], a[mi], bf[ni][2], bf[ni][3]);
            }
    };

    uint32_t a0[2][4], b0[4][4], a1[2][4], b1[4][4];

    const int NK = KC / BK;  // 34
    load_stage(0); load_stage(1); load_stage(2);       // 3 groups in flight
    asm volatile("cp.async.wait_group 2;\n");          // group 0 landed
    __syncthreads();
    ldsm_half(0, 0, a0, b0);                           // f0 = (s=0, kk=0)

    for (int s = 0; s < NK; ++s) {
        ldsm_half(s, 16, a1, b1);      // f1 = (s, kk=1)
        mma_half(a0, b0);              // compute (s,0) under f1's LDSM
        // this thread's group s+1 must be complete before ldsm(s+1):
        if (s + 2 < NK) { asm volatile("cp.async.wait_group 1;\n"); }
        else            { asm volatile("cp.async.wait_group 0;\n"); }
        __syncthreads();               // global visibility of slot s+1;
                                       // also: last reads of slot (s+3)%4==(s-1)%4
                                       // happened before this barrier
        if (s + 3 < NK) load_stage(s + 3);
        if (s + 1 < NK) ldsm_half(s + 1, 0, a0, b0);   // f0 = (s+1, kk=0)
        mma_half(a1, b1);              // compute (s,1) under cp.async + f0's LDSM
    }

    // epilogue: tanh + weighted reduce over this CTA's 128 d-columns
    #pragma unroll
    for (int mi = 0; mi < 2; mi++) {
        float s0 = 0.f, s1 = 0.f;   // rows (lane>>2) and (lane>>2)+8
        #pragma unroll
        for (int j = 0; j < 8; j++) {
            int nc = wn + j*8 + 2*(lane & 3);
            float qb0 = qb_s[nc], qb1 = qb_s[nc+1];
            float w0 = ws_s[nc],  w1 = ws_s[nc+1];
            s0 += tanhf(acc[mi][j][0] + qb0)*w0 + tanhf(acc[mi][j][1] + qb1)*w1;
            s1 += tanhf(acc[mi][j][2] + qb0)*w0 + tanhf(acc[mi][j][3] + qb1)*w1;
        }
        s0 += __shfl_xor_sync(0xffffffffu, s0, 1);
        s0 += __shfl_xor_sync(0xffffffffu, s0, 2);
        s1 += __shfl_xor_sync(0xffffffffu, s1, 1);
        s1 += __shfl_xor_sync(0xffffffffu, s1, 2);
        if ((lane & 3) == 0) {
            int m0 = bm0 + wm + mi*16 + (lane >> 2);
            atomicAdd(&g_score[m0],     s0);
            atomicAdd(&g_score[m0 + 8], s1);
        }
    }
}

// ---------------- sigmoid + normalize -> attn (also zero context) ----------------
__global__ void normalize_kernel(const float* __restrict__ b_score, float* __restrict__ attn_out,
                                 int write_attn) {
    int b = blockIdx.x, t = threadIdx.x;     // 256 threads, 2048 elems
    __shared__ float red[256];
    for (int h = t; h < H_; h += 256) g_context[b*H_ + h] = 0.f;
    float bs = b_score[0];
    float sv[8];
    float local = 0.f;
    #pragma unroll
    for (int i = 0; i < 8; i++) {
        float x = g_score[b*VLEN_ + t + i*256] + bs;
        float s = 1.f / (1.f + __expf(-x));
        sv[i] = s; local += s;
    }
    red[t] = local; __syncthreads();
    #pragma unroll
    for (int o = 128; o; o >>= 1) { if (t < o) red[t] += red[t+o]; __syncthreads(); }
    float inv = 1.f / red[0];
    #pragma unroll
    for (int i = 0; i < 8; i++) {
        float a = sv[i] * inv;
        g_attn[b*VLEN_ + t + i*256] = a;
        if (write_attn) attn_out[b*VLEN_ + t + i*256] = a;
    }
}

// ---------------- context[b,h] = sum_v attn[b,v] * value[b,v,h] ----------------
__global__ void context_kernel(const float* __restrict__ value) {
    int hc = blockIdx.x, b = blockIdx.y, vs = blockIdx.z;   // (4, B, 8)
    int h = hc*256 + threadIdx.x;
    __shared__ float a_s[256];
    a_s[threadIdx.x] = g_attn[b*VLEN_ + vs*256 + threadIdx.x];
    __syncthreads();
    const float* vp = value + ((size_t)b*VLEN_ + vs*256)*H_ + h;
    float acc = 0.f;
    #pragma unroll 8
    for (int v = 0; v < 256; v++) acc += a_s[v] * vp[(size_t)v*H_];
    atomicAdd(&g_context[b*H_ + h], acc);
}

// ---------------- output[b,h] = w_out[h] . [context | query] + b_out[h] ----------------
__global__ void output_kernel(const float* __restrict__ w_out, const float* __restrict__ b_out,
                              const float* __restrict__ query, float* __restrict__ out) {
    int b = blockIdx.y;
    int warp = threadIdx.x >> 5, lane = threadIdx.x & 31;
    int h = blockIdx.x*8 + warp;
    const float* wr = w_out + (size_t)h*(2*H_);
    const float* ctx = g_context + b*H_;
    const float* q = query + b*H_;
    float acc = 0.f;
    for (int k = lane; k < H_; k += 32) acc += wr[k]*ctx[k];
    for (int k = lane; k < H_; k += 32) acc += wr[H_+k]*q[k];
    #pragma unroll
    for (int o = 16; o; o >>= 1) acc += __shfl_xor_sync(0xffffffffu, acc, o);
    if (!lane) out[b*H_ + h] = acc + b_out[h];
}

// ---------------- launch ----------------
extern "C" void kernel_launch(void* const* d_in, const int* in_sizes, int n_in,
                              void* d_out, int out_size) {
    const float* query     = (const float*)d_in[0];
    const float* value     = (const float*)d_in[1];
    const float* prev_attn = (const float*)d_in[2];
    const float* conv_w    = (const float*)d_in[3];
    const float* conv_b    = (const float*)d_in[4];
    const float* w_loc     = (const float*)d_in[5];
    const float* w_q       = (const float*)d_in[6];
    const float* w_v       = (const float*)d_in[7];
    const float* bias      = (const float*)d_in[8];
    const float* w_score   = (const float*)d_in[9];
    const float* b_score   = (const float*)d_in[10];
    const float* w_out     = (const float*)d_in[11];
    const float* b_out     = (const float*)d_in[12];
    float* out = (float*)d_out;

    (void)in_sizes; (void)n_in;

    cudaFuncSetAttribute(gemm_score_kernel,
                         cudaFuncAttributeMaxDynamicSharedMemorySize, SMEM_TOTAL_GEMM);

    build_valcat<<< (M_*(KC/8))/256, 256 >>>(value, prev_attn, conv_w, conv_b);
    build_wcat<<< (DIM_*(KC/8) + 255)/256, 256 >>>(w_v, w_loc);
    qbias_kernel<<< dim3(DIM_/8, B_), 256 >>>(query, w_q, bias);
    gemm_score_kernel<<< dim3(DIM_/BN, M_/BM), 256, SMEM_TOTAL_GEMM >>>(w_score);

    int write_attn = (out_size >= B_*H_ + M_) ? 1 : 0;   // output first, then attn
    normalize_kernel<<< B_, 256 >>>(b_score, out + B_*H_, write_attn);
    context_kernel<<< dim3(H_/256, B_, VLEN_/256), 256 >>>(value);
    output_kernel<<< dim3(H_/8, B_), 256 >>>(w_out, b_out, query, out);
}

// round 9
// speedup vs baseline: 1.1783x; 1.0602x over previous
#include <cuda_runtime.h>
#include <cuda_bf16.h>
#include <cstdint>

#define B_    32
#define VLEN_ 2048
#define H_    1024
#define DIM_  1024
#define C_    32
#define KC    1088              // 1024 (value) + 32 (conv feat) + 32 zero pad
#define M_    (B_*VLEN_)        // 65536

// ---------------- scratch (device globals: no runtime allocation) ----------------
__device__ __nv_bfloat16 g_valcat[(size_t)M_*KC];    // [65536][1088] bf16  (~142 MB)
__device__ __nv_bfloat16 g_wcat[(size_t)DIM_*KC];    // [1024][1088] bf16
__device__ float g_qbias[B_*DIM_];                   // qp[b,d] + bias[d]
__device__ float g_score[M_];
__device__ float g_attn[M_];
__device__ float g_context[B_*H_];

__device__ __forceinline__ uint32_t smem_u32(const void* p){
    return (uint32_t)__cvta_generic_to_shared(p);
}

// -------- prep: A matrix = [value(bf16) | conv_feat(bf16) | 0]; also zeroes g_score --------
__global__ void build_valcat(const float* __restrict__ value,
                             const float* __restrict__ prev_attn,
                             const float* __restrict__ conv_w,
                             const float* __restrict__ conv_b) {
    int t = blockIdx.x*256 + threadIdx.x;               // one 16B chunk each
    const int CHUNKS = KC/8;                            // 136
    if (t < M_) g_score[t] = 0.f;                       // fused zero_score
    if (t >= M_*CHUNKS) return;
    int bv = t / CHUNKS, chunk = t % CHUNKS;
    __align__(16) __nv_bfloat16 o[8];
    if (chunk < 128) {
        const float4* s = reinterpret_cast<const float4*>(value + (size_t)bv*H_ + chunk*8);
        float4 x = s[0], y = s[1];
        o[0]=__float2bfloat16(x.x); o[1]=__float2bfloat16(x.y);
        o[2]=__float2bfloat16(x.z); o[3]=__float2bfloat16(x.w);
        o[4]=__float2bfloat16(y.x); o[5]=__float2bfloat16(y.y);
        o[6]=__float2bfloat16(y.z); o[7]=__float2bfloat16(y.w);
    } else if (chunk < 132) {
        int b = bv >> 11, v = bv & 2047;
        float pm = (v > 0)        ? prev_attn[b*VLEN_ + v - 1] : 0.f;
        float pc =                  prev_attn[b*VLEN_ + v];
        float pp = (v < VLEN_-1)  ? prev_attn[b*VLEN_ + v + 1] : 0.f;
        int c0 = (chunk-128)*8;
        #pragma unroll
        for (int j = 0; j < 8; j++) {
            int c = c0 + j;
            float cf = conv_w[c*3+0]*pm + conv_w[c*3+1]*pc + conv_w[c*3+2]*pp + conv_b[c];
            o[j] = __float2bfloat16(cf);
        }
    } else {
        #pragma unroll
        for (int j = 0; j < 8; j++) o[j] = __float2bfloat16(0.f);
    }
    *reinterpret_cast<uint4*>(g_valcat + (size_t)bv*KC + chunk*8) = *reinterpret_cast<uint4*>(o);
}

// ---------------- prep: B matrix = [w_v | w_loc | 0] ----------------
__global__ void build_wcat(const float* __restrict__ w_v, const float* __restrict__ w_loc) {
    int t = blockIdx.x*256 + threadIdx.x;
    const int CHUNKS = KC/8;
    if (t >= DIM_*CHUNKS) return;
    int d = t / CHUNKS, chunk = t % CHUNKS;
    __align__(16) __nv_bfloat16 o[8];
    if (chunk < 128) {
        const float* s = w_v + (size_t)d*H_ + chunk*8;
        #pragma unroll
        for (int j = 0; j < 8; j++) o[j] = __float2bfloat16(s[j]);
    } else if (chunk < 132) {
        const float* s = w_loc + (size_t)d*C_ + (chunk-128)*8;
        #pragma unroll
        for (int j = 0; j < 8; j++) o[j] = __float2bfloat16(s[j]);
    } else {
        #pragma unroll
        for (int j = 0; j < 8; j++) o[j] = __float2bfloat16(0.f);
    }
    *reinterpret_cast<uint4*>(g_wcat + (size_t)d*KC + chunk*8) = *reinterpret_cast<uint4*>(o);
}

// ---------------- prep: qbias[b,d] = query[b] . w_q[d] + bias[d] (fp32 exact) ----------------
__global__ void qbias_kernel(const float* __restrict__ query,
                             const float* __restrict__ w_q,
                             const float* __restrict__ bias) {
    int b = blockIdx.y;
    int warp = threadIdx.x >> 5, lane = threadIdx.x & 31;
    int d = blockIdx.x*8 + warp;
    const float* q = query + b*H_;
    const float* w = w_q + (size_t)d*H_;
    float acc = 0.f;
    for (int h = lane; h < H_; h += 32) acc += q[h]*w[h];
    #pragma unroll
    for (int o = 16; o; o >>= 1) acc += __shfl_xor_sync(0xffffffffu, acc, o);
    if (!lane) g_qbias[b*DIM_ + d] = acc + bias[d];
}

// ---------------- fused GEMM + tanh + score reduction (HMMA path) ----------------
// C[m,n] = sum_k A[m,k]*B[n,k] ; score[m] += sum_n tanh(C + qbias[b,n]) * w_score[n]
// BM=128, BN=128, 8 warps (4 along M x 2 along N), warp tile 32x64.
// KTILE=64 stages (17 total): ONE wait+barrier per 64-k, 4 kk-halves of
// uninterrupted ldsm/mma ping-pong per stage. STG=3, 110.6KB smem, 2 CTAs/SM.
#define BM 128
#define BN 128
#define KTILE 64
#define NSTG  (KC/KTILE)   // 17
#define STG 3
#define KPAD 72            // 64 + 8 pad (144B rows -> conflict-free ldmatrix)

#define A_STG_ELEMS (BM*KPAD)            // 9216
#define B_STG_ELEMS (BN*KPAD)            // 9216
#define SM_A_OFF 0
#define SM_B_OFF (STG*A_STG_ELEMS*2)                    // 55296
#define SM_QB_OFF (SM_B_OFF + STG*B_STG_ELEMS*2)        // 110592
#define SM_WS_OFF (SM_QB_OFF + BN*4)
#define SMEM_TOTAL_GEMM (SM_WS_OFF + BN*4)              // 111616

__device__ __forceinline__ void mma16816(float* c, const uint32_t* a, uint32_t b0, uint32_t b1) {
    asm volatile("mma.sync.aligned.m16n8k16.row.col.f32.bf16.bf16.f32 "
                 "{%0,%1,%2,%3}, {%4,%5,%6,%7}, {%8,%9}, {%0,%1,%2,%3};"
                 : "+f"(c[0]), "+f"(c[1]), "+f"(c[2]), "+f"(c[3])
                 : "r"(a[0]), "r"(a[1]), "r"(a[2]), "r"(a[3]), "r"(b0), "r"(b1));
}

__global__ __launch_bounds__(256, 2)
void gemm_score_kernel(const float* __restrict__ w_score) {
    extern __shared__ __align__(16) char sm[];
    __nv_bfloat16* As = reinterpret_cast<__nv_bfloat16*>(sm + SM_A_OFF);  // [STG][BM][KPAD]
    __nv_bfloat16* Bs = reinterpret_cast<__nv_bfloat16*>(sm + SM_B_OFF);  // [STG][BN][KPAD]
    float* qb_s = reinterpret_cast<float*>(sm + SM_QB_OFF);
    float* ws_s = reinterpret_cast<float*>(sm + SM_WS_OFF);

    const int t = threadIdx.x;
    const int warp = t >> 5, lane = t & 31;
    const int bn0 = blockIdx.x * BN;   // x fastest -> n-CTAs of one m-block co-resident
    const int bm0 = blockIdx.y * BM;
    const int batch = bm0 >> 11;       // 2048 rows per batch; BM | 2048

    if (t < BN) {
        qb_s[t] = g_qbias[batch*DIM_ + bn0 + t];
        ws_s[t] = w_score[bn0 + t];
    }

    // stage loader: 128 rows x 8 chunks(16B) per matrix; 256 thr -> 4+4 chunks each
    const int lrow = t >> 3;      // 0..31
    const int lch  = t & 7;       // 16B chunk within 128B row
    const __nv_bfloat16* Ag = g_valcat + (size_t)bm0*KC + lch*8;
    const __nv_bfloat16* Bg = g_wcat   + (size_t)bn0*KC + lch*8;

    const int wm = (warp >> 1) * 32;   // 4 warps along M
    const int wn = (warp & 1) * 64;    // 2 warps along N
    const int g = lane >> 3, idx = lane & 7;
    const int a_row0 = wm + idx + 8*(g & 1);      // + mi*16
    const int a_col0 = 8*(g >> 1);                // + kb
    const int b_row0 = wn + idx + 8*(g >> 1);     // + ni*16
    const int b_col0 = 8*(g & 1);                 // + kb

    float acc[2][8][4];
    #pragma unroll
    for (int i = 0; i < 2; i++)
        #pragma unroll
        for (int j = 0; j < 8; j++)
            #pragma unroll
            for (int k = 0; k < 4; k++) acc[i][j][k] = 0.f;

    auto load_stage = [&](int s) {
        int slot = s % STG;
        int k0 = s * KTILE;
        __nv_bfloat16* Ad = As + slot*A_STG_ELEMS;
        __nv_bfloat16* Bd = Bs + slot*B_STG_ELEMS;
        #pragma unroll
        for (int i = 0; i < 4; i++) {
            int r = lrow + i*32;
            uint32_t d = smem_u32(Ad + r*KPAD + lch*8);
            asm volatile("cp.async.cg.shared.global [%0], [%1], 16;\n"
                         :: "r"(d), "l"(Ag + (size_t)r*KC + k0));
            uint32_t db = smem_u32(Bd + r*KPAD + lch*8);
            asm volatile("cp.async.cg.shared.global [%0], [%1], 16;\n"
                         :: "r"(db), "l"(Bg + (size_t)r*KC + k0));
        }
        asm volatile("cp.async.commit_group;\n");
    };

    // load one kk-half's fragments (6 ldmatrix.x4); kb in {0,16,32,48}
    auto ldsm_half = [&](int s, int kb, uint32_t a[2][4], uint32_t bf[4][4]) {
        const __nv_bfloat16* Asl = As + (s % STG)*A_STG_ELEMS;
        const __nv_bfloat16* Bsl = Bs + (s % STG)*B_STG_ELEMS;
        #pragma unroll
        for (int mi = 0; mi < 2; mi++) {
            uint32_t addr = smem_u32(Asl + (a_row0 + mi*16)*KPAD + a_col0 + kb);
            asm volatile("ldmatrix.sync.aligned.m8n8.x4.shared.b16 {%0,%1,%2,%3}, [%4];"
                         : "=r"(a[mi][0]), "=r"(a[mi][1]), "=r"(a[mi][2]), "=r"(a[mi][3])
                         : "r"(addr));
        }
        #pragma unroll
        for (int ni = 0; ni < 4; ni++) {
            uint32_t addr = smem_u32(Bsl + (b_row0 + ni*16)*KPAD + b_col0 + kb);
            asm volatile("ldmatrix.sync.aligned.m8n8.x4.shared.b16 {%0,%1,%2,%3}, [%4];"
                         : "=r"(bf[ni][0]), "=r"(bf[ni][1]), "=r"(bf[ni][2]), "=r"(bf[ni][3])
                         : "r"(addr));
        }
    };

    auto mma_half = [&](uint32_t a[2][4], uint32_t bf[4][4]) {
        #pragma unroll
        for (int mi = 0; mi < 2; mi++)
            #pragma unroll
            for (int ni = 0; ni < 4; ni++) {
                mma16816(acc[mi][ni*2+0], a[mi], bf[ni][0], bf[ni][1]);
                mma16816(acc[mi][ni*2+1], a[mi], bf[ni][2], bf[ni][3]);
            }
    };

    uint32_t a0[2][4], b0[4][4], a1[2][4], b1[4][4];

    // prologue: 3 groups in flight; stage 0 landed before first ldsm
    load_stage(0); load_stage(1); load_stage(2);
    asm volatile("cp.async.wait_group 2;\n");
    __syncthreads();
    ldsm_half(0, 0, a0, b0);

    for (int s = 0; s < NSTG; ++s) {
        // 4 kk-halves of ping-pong, no barriers inside
        ldsm_half(s, 16, a1, b1);  mma_half(a0, b0);
        ldsm_half(s, 32, a0, b0);  mma_half(a1, b1);
        ldsm_half(s, 48, a1, b1);  mma_half(a0, b0);
        if (s + 1 < NSTG) {
            // stage s+1 landed (own groups), then cross-thread visibility
            if (s == NSTG - 2) { asm volatile("cp.async.wait_group 0;\n"); }
            else               { asm volatile("cp.async.wait_group 1;\n"); }
            __syncthreads();   // also: all warps done reading stage s (slot s%3)
            if (s + 3 < NSTG) load_stage(s + 3);   // slot (s+3)%3 == s%3: safe
            ldsm_half(s + 1, 0, a0, b0);
        }
        mma_half(a1, b1);
    }

    // epilogue: tanh + weighted reduce over this CTA's 128 d-columns
    #pragma unroll
    for (int mi = 0; mi < 2; mi++) {
        float s0 = 0.f, s1 = 0.f;   // rows (lane>>2) and (lane>>2)+8
        #pragma unroll
        for (int j = 0; j < 8; j++) {
            int nc = wn + j*8 + 2*(lane & 3);
            float qb0 = qb_s[nc], qb1 = qb_s[nc+1];
            float w0 = ws_s[nc],  w1 = ws_s[nc+1];
            s0 += tanhf(acc[mi][j][0] + qb0)*w0 + tanhf(acc[mi][j][1] + qb1)*w1;
            s1 += tanhf(acc[mi][j][2] + qb0)*w0 + tanhf(acc[mi][j][3] + qb1)*w1;
        }
        s0 += __shfl_xor_sync(0xffffffffu, s0, 1);
        s0 += __shfl_xor_sync(0xffffffffu, s0, 2);
        s1 += __shfl_xor_sync(0xffffffffu, s1, 1);
        s1 += __shfl_xor_sync(0xffffffffu, s1, 2);
        if ((lane & 3) == 0) {
            int m0 = bm0 + wm + mi*16 + (lane >> 2);
            atomicAdd(&g_score[m0],     s0);
            atomicAdd(&g_score[m0 + 8], s1);
        }
    }
}

// ---------------- sigmoid + normalize -> attn (also zero context) ----------------
__global__ void normalize_kernel(const float* __restrict__ b_score, float* __restrict__ attn_out,
                                 int write_attn) {
    int b = blockIdx.x, t = threadIdx.x;     // 256 threads, 2048 elems
    __shared__ float red[256];
    for (int h = t; h < H_; h += 256) g_context[b*H_ + h] = 0.f;
    float bs = b_score[0];
    float sv[8];
    float local = 0.f;
    #pragma unroll
    for (int i = 0; i < 8; i++) {
        float x = g_score[b*VLEN_ + t + i*256] + bs;
        float s = 1.f / (1.f + __expf(-x));
        sv[i] = s; local += s;
    }
    red[t] = local; __syncthreads();
    #pragma unroll
    for (int o = 128; o; o >>= 1) { if (t < o) red[t] += red[t+o]; __syncthreads(); }
    float inv = 1.f / red[0];
    #pragma unroll
    for (int i = 0; i < 8; i++) {
        float a = sv[i] * inv;
        g_attn[b*VLEN_ + t + i*256] = a;
        if (write_attn) attn_out[b*VLEN_ + t + i*256] = a;
    }
}

// ---------------- context[b,h] = sum_v attn[b,v] * value[b,v,h] ----------------
__global__ void context_kernel(const float* __restrict__ value) {
    int hc = blockIdx.x, b = blockIdx.y, vs = blockIdx.z;   // (4, B, 8)
    int h = hc*256 + threadIdx.x;
    __shared__ float a_s[256];
    a_s[threadIdx.x] = g_attn[b*VLEN_ + vs*256 + threadIdx.x];
    __syncthreads();
    const float* vp = value + ((size_t)b*VLEN_ + vs*256)*H_ + h;
    float acc = 0.f;
    #pragma unroll 8
    for (int v = 0; v < 256; v++) acc += a_s[v] * vp[(size_t)v*H_];
    atomicAdd(&g_context[b*H_ + h], acc);
}

// ---------------- output[b,h] = w_out[h] . [context | query] + b_out[h] ----------------
__global__ void output_kernel(const float* __restrict__ w_out, const float* __restrict__ b_out,
                              const float* __restrict__ query, float* __restrict__ out) {
    int b = blockIdx.y;
    int warp = threadIdx.x >> 5, lane = threadIdx.x & 31;
    int h = blockIdx.x*8 + warp;
    const float* wr = w_out + (size_t)h*(2*H_);
    const float* ctx = g_context + b*H_;
    const float* q = query + b*H_;
    float acc = 0.f;
    for (int k = lane; k < H_; k += 32) acc += wr[k]*ctx[k];
    for (int k = lane; k < H_; k += 32) acc += wr[H_+k]*q[k];
    #pragma unroll
    for (int o = 16; o; o >>= 1) acc += __shfl_xor_sync(0xffffffffu, acc, o);
    if (!lane) out[b*H_ + h] = acc + b_out[h];
}

// ---------------- launch ----------------
extern "C" void kernel_launch(void* const* d_in, const int* in_sizes, int n_in,
                              void* d_out, int out_size) {
    const float* query     = (const float*)d_in[0];
    const float* value     = (const float*)d_in[1];
    const float* prev_attn = (const float*)d_in[2];
    const float* conv_w    = (const float*)d_in[3];
    const float* conv_b    = (const float*)d_in[4];
    const float* w_loc     = (const float*)d_in[5];
    const float* w_q       = (const float*)d_in[6];
    const float* w_v       = (const float*)d_in[7];
    const float* bias      = (const float*)d_in[8];
    const float* w_score   = (const float*)d_in[9];
    const float* b_score   = (const float*)d_in[10];
    const float* w_out     = (const float*)d_in[11];
    const float* b_out     = (const float*)d_in[12];
    float* out = (float*)d_out;

    (void)in_sizes; (void)n_in;

    cudaFuncSetAttribute(gemm_score_kernel,
                         cudaFuncAttributeMaxDynamicSharedMemorySize, SMEM_TOTAL_GEMM);

    build_valcat<<< (M_*(KC/8))/256, 256 >>>(value, prev_attn, conv_w, conv_b);
    build_wcat<<< (DIM_*(KC/8) + 255)/256, 256 >>>(w_v, w_loc);
    qbias_kernel<<< dim3(DIM_/8, B_), 256 >>>(query, w_q, bias);
    gemm_score_kernel<<< dim3(DIM_/BN, M_/BM), 256, SMEM_TOTAL_GEMM >>>(w_score);

    int write_attn = (out_size >= B_*H_ + M_) ? 1 : 0;   // output first, then attn
    normalize_kernel<<< B_, 256 >>>(b_score, out + B_*H_, write_attn);
    context_kernel<<< dim3(H_/256, B_, VLEN_/256), 256 >>>(value);
    output_kernel<<< dim3(H_/8, B_), 256 >>>(w_out, b_out, query, out);
}

// round 10
// speedup vs baseline: 1.1975x; 1.0163x over previous
#include <cuda_runtime.h>
#include <cuda_bf16.h>
#include <cstdint>

#define B_    32
#define VLEN_ 2048
#define H_    1024
#define DIM_  1024
#define C_    32
#define KC    1088              // 1024 (value) + 32 (conv feat) + 32 zero pad
#define M_    (B_*VLEN_)        // 65536

// ---------------- scratch (device globals: no runtime allocation) ----------------
__device__ __nv_bfloat16 g_valcat[(size_t)M_*KC];    // [65536][1088] bf16  (~142 MB)
__device__ __nv_bfloat16 g_wcat[(size_t)DIM_*KC];    // [1024][1088] bf16
__device__ float g_qbias[B_*DIM_];                   // qp[b,d] + bias[d]
__device__ float g_score[M_];
__device__ float g_attn[M_];
__device__ float g_context[B_*H_];

__device__ __forceinline__ uint32_t smem_u32(const void* p){
    return (uint32_t)__cvta_generic_to_shared(p);
}

// -------- prep: A matrix = [value(bf16) | conv_feat(bf16) | 0]; also zeroes g_score --------
__global__ void build_valcat(const float* __restrict__ value,
                             const float* __restrict__ prev_attn,
                             const float* __restrict__ conv_w,
                             const float* __restrict__ conv_b) {
    int t = blockIdx.x*256 + threadIdx.x;               // one 16B chunk each
    const int CHUNKS = KC/8;                            // 136
    if (t < M_) g_score[t] = 0.f;                       // fused zero_score
    if (t >= M_*CHUNKS) return;
    int bv = t / CHUNKS, chunk = t % CHUNKS;
    __align__(16) __nv_bfloat16 o[8];
    if (chunk < 128) {
        const float4* s = reinterpret_cast<const float4*>(value + (size_t)bv*H_ + chunk*8);
        float4 x = s[0], y = s[1];
        o[0]=__float2bfloat16(x.x); o[1]=__float2bfloat16(x.y);
        o[2]=__float2bfloat16(x.z); o[3]=__float2bfloat16(x.w);
        o[4]=__float2bfloat16(y.x); o[5]=__float2bfloat16(y.y);
        o[6]=__float2bfloat16(y.z); o[7]=__float2bfloat16(y.w);
    } else if (chunk < 132) {
        int b = bv >> 11, v = bv & 2047;
        float pm = (v > 0)        ? prev_attn[b*VLEN_ + v - 1] : 0.f;
        float pc =                  prev_attn[b*VLEN_ + v];
        float pp = (v < VLEN_-1)  ? prev_attn[b*VLEN_ + v + 1] : 0.f;
        int c0 = (chunk-128)*8;
        #pragma unroll
        for (int j = 0; j < 8; j++) {
            int c = c0 + j;
            float cf = conv_w[c*3+0]*pm + conv_w[c*3+1]*pc + conv_w[c*3+2]*pp + conv_b[c];
            o[j] = __float2bfloat16(cf);
        }
    } else {
        #pragma unroll
        for (int j = 0; j < 8; j++) o[j] = __float2bfloat16(0.f);
    }
    *reinterpret_cast<uint4*>(g_valcat + (size_t)bv*KC + chunk*8) = *reinterpret_cast<uint4*>(o);
}

// ---------------- prep: B matrix = [w_v | w_loc | 0] ----------------
__global__ void build_wcat(const float* __restrict__ w_v, const float* __restrict__ w_loc) {
    int t = blockIdx.x*256 + threadIdx.x;
    const int CHUNKS = KC/8;
    if (t >= DIM_*CHUNKS) return;
    int d = t / CHUNKS, chunk = t % CHUNKS;
    __align__(16) __nv_bfloat16 o[8];
    if (chunk < 128) {
        const float* s = w_v + (size_t)d*H_ + chunk*8;
        #pragma unroll
        for (int j = 0; j < 8; j++) o[j] = __float2bfloat16(s[j]);
    } else if (chunk < 132) {
        const float* s = w_loc + (size_t)d*C_ + (chunk-128)*8;
        #pragma unroll
        for (int j = 0; j < 8; j++) o[j] = __float2bfloat16(s[j]);
    } else {
        #pragma unroll
        for (int j = 0; j < 8; j++) o[j] = __float2bfloat16(0.f);
    }
    *reinterpret_cast<uint4*>(g_wcat + (size_t)d*KC + chunk*8) = *reinterpret_cast<uint4*>(o);
}

// ---------------- prep: qbias[b,d] = query[b] . w_q[d] + bias[d] (fp32 exact) ----------------
__global__ void qbias_kernel(const float* __restrict__ query,
                             const float* __restrict__ w_q,
                             const float* __restrict__ bias) {
    int b = blockIdx.y;
    int warp = threadIdx.x >> 5, lane = threadIdx.x & 31;
    int d = blockIdx.x*8 + warp;
    const float* q = query + b*H_;
    const float* w = w_q + (size_t)d*H_;
    float acc = 0.f;
    for (int h = lane; h < H_; h += 32) acc += q[h]*w[h];
    #pragma unroll
    for (int o = 16; o; o >>= 1) acc += __shfl_xor_sync(0xffffffffu, acc, o);
    if (!lane) g_qbias[b*DIM_ + d] = acc + bias[d];
}

// ---------------- fused GEMM + tanh + score reduction (HMMA path) ----------------
// C[m,n] = sum_k A[m,k]*B[n,k] ; score[m] += sum_n tanh(C + qbias[b,n]) * w_score[n]
// BM=128, BN=128, 8 warps (4 along M x 2 along N), warp tile 32x64.
// KTILE=64 stages (17 total): ONE wait+barrier per 64-k, 4 kk-halves of
// ldsm/mma ping-pong per stage. mma is NON-volatile: ptxas may interleave
// HMMA with LDSM/ALU freely (register deps keep correctness).
#define BM 128
#define BN 128
#define KTILE 64
#define NSTG  (KC/KTILE)   // 17
#define STG 3
#define KPAD 72            // 64 + 8 pad (144B rows -> conflict-free ldmatrix)

#define A_STG_ELEMS (BM*KPAD)            // 9216
#define B_STG_ELEMS (BN*KPAD)            // 9216
#define SM_A_OFF 0
#define SM_B_OFF (STG*A_STG_ELEMS*2)                    // 55296
#define SM_QB_OFF (SM_B_OFF + STG*B_STG_ELEMS*2)        // 110592
#define SM_WS_OFF (SM_QB_OFF + BN*4)
#define SMEM_TOTAL_GEMM (SM_WS_OFF + BN*4)              // 111616

__device__ __forceinline__ void mma16816(float* c, const uint32_t* a, uint32_t b0, uint32_t b1) {
    // non-volatile: register-only op, let ptxas schedule it
    asm("mma.sync.aligned.m16n8k16.row.col.f32.bf16.bf16.f32 "
        "{%0,%1,%2,%3}, {%4,%5,%6,%7}, {%8,%9}, {%0,%1,%2,%3};"
        : "+f"(c[0]), "+f"(c[1]), "+f"(c[2]), "+f"(c[3])
        : "r"(a[0]), "r"(a[1]), "r"(a[2]), "r"(a[3]), "r"(b0), "r"(b1));
}

__global__ __launch_bounds__(256, 2)
void gemm_score_kernel(const float* __restrict__ w_score) {
    extern __shared__ __align__(16) char sm[];
    __nv_bfloat16* As = reinterpret_cast<__nv_bfloat16*>(sm + SM_A_OFF);  // [STG][BM][KPAD]
    __nv_bfloat16* Bs = reinterpret_cast<__nv_bfloat16*>(sm + SM_B_OFF);  // [STG][BN][KPAD]
    float* qb_s = reinterpret_cast<float*>(sm + SM_QB_OFF);
    float* ws_s = reinterpret_cast<float*>(sm + SM_WS_OFF);

    const int t = threadIdx.x;
    const int warp = t >> 5, lane = t & 31;
    const int bn0 = blockIdx.x * BN;   // x fastest -> n-CTAs of one m-block co-resident
    const int bm0 = blockIdx.y * BM;
    const int batch = bm0 >> 11;       // 2048 rows per batch; BM | 2048

    if (t < BN) {
        qb_s[t] = g_qbias[batch*DIM_ + bn0 + t];
        ws_s[t] = w_score[bn0 + t];
    }

    // stage loader: 128 rows x 8 chunks(16B) per matrix; 256 thr -> 4+4 chunks each
    const int lrow = t >> 3;      // 0..31
    const int lch  = t & 7;       // 16B chunk within 128B row
    const __nv_bfloat16* Ag = g_valcat + (size_t)bm0*KC + lch*8;
    const __nv_bfloat16* Bg = g_wcat   + (size_t)bn0*KC + lch*8;

    const int wm = (warp >> 1) * 32;   // 4 warps along M
    const int wn = (warp & 1) * 64;    // 2 warps along N
    const int g = lane >> 3, idx = lane & 7;
    const int a_row0 = wm + idx + 8*(g & 1);      // + mi*16
    const int a_col0 = 8*(g >> 1);                // + kb
    const int b_row0 = wn + idx + 8*(g >> 1);     // + ni*16
    const int b_col0 = 8*(g & 1);                 // + kb

    float acc[2][8][4];
    #pragma unroll
    for (int i = 0; i < 2; i++)
        #pragma unroll
        for (int j = 0; j < 8; j++)
            #pragma unroll
            for (int k = 0; k < 4; k++) acc[i][j][k] = 0.f;

    auto load_stage = [&](int s) {
        int slot = s % STG;
        int k0 = s * KTILE;
        __nv_bfloat16* Ad = As + slot*A_STG_ELEMS;
        __nv_bfloat16* Bd = Bs + slot*B_STG_ELEMS;
        #pragma unroll
        for (int i = 0; i < 4; i++) {
            int r = lrow + i*32;
            uint32_t d = smem_u32(Ad + r*KPAD + lch*8);
            asm volatile("cp.async.cg.shared.global [%0], [%1], 16;\n"
                         :: "r"(d), "l"(Ag + (size_t)r*KC + k0));
            uint32_t db = smem_u32(Bd + r*KPAD + lch*8);
            asm volatile("cp.async.cg.shared.global [%0], [%1], 16;\n"
                         :: "r"(db), "l"(Bg + (size_t)r*KC + k0));
        }
        asm volatile("cp.async.commit_group;\n");
    };

    // load one kk-half's fragments (6 ldmatrix.x4); kb in {0,16,32,48}
    auto ldsm_half = [&](int s, int kb, uint32_t a[2][4], uint32_t bf[4][4]) {
        const __nv_bfloat16* Asl = As + (s % STG)*A_STG_ELEMS;
        const __nv_bfloat16* Bsl = Bs + (s % STG)*B_STG_ELEMS;
        #pragma unroll
        for (int mi = 0; mi < 2; mi++) {
            uint32_t addr = smem_u32(Asl + (a_row0 + mi*16)*KPAD + a_col0 + kb);
            asm volatile("ldmatrix.sync.aligned.m8n8.x4.shared.b16 {%0,%1,%2,%3}, [%4];"
                         : "=r"(a[mi][0]), "=r"(a[mi][1]), "=r"(a[mi][2]), "=r"(a[mi][3])
                         : "r"(addr));
        }
        #pragma unroll
        for (int ni = 0; ni < 4; ni++) {
            uint32_t addr = smem_u32(Bsl + (b_row0 + ni*16)*KPAD + b_col0 + kb);
            asm volatile("ldmatrix.sync.aligned.m8n8.x4.shared.b16 {%0,%1,%2,%3}, [%4];"
                         : "=r"(bf[ni][0]), "=r"(bf[ni][1]), "=r"(bf[ni][2]), "=r"(bf[ni][3])
                         : "r"(addr));
        }
    };

    auto mma_half = [&](uint32_t a[2][4], uint32_t bf[4][4]) {
        #pragma unroll
        for (int mi = 0; mi < 2; mi++)
            #pragma unroll
            for (int ni = 0; ni < 4; ni++) {
                mma16816(acc[mi][ni*2+0], a[mi], bf[ni][0], bf[ni][1]);
                mma16816(acc[mi][ni*2+1], a[mi], bf[ni][2], bf[ni][3]);
            }
    };

    uint32_t a0[2][4], b0[4][4], a1[2][4], b1[4][4];

    // prologue: 3 groups in flight; stage 0 landed before first ldsm
    load_stage(0); load_stage(1); load_stage(2);
    asm volatile("cp.async.wait_group 2;\n");
    __syncthreads();
    ldsm_half(0, 0, a0, b0);

    for (int s = 0; s < NSTG; ++s) {
        // 4 kk-halves of ping-pong, no barriers inside
        ldsm_half(s, 16, a1, b1);  mma_half(a0, b0);
        ldsm_half(s, 32, a0, b0);  mma_half(a1, b1);
        ldsm_half(s, 48, a1, b1);  mma_half(a0, b0);
        if (s + 1 < NSTG) {
            // stage s+1 landed (own groups), then cross-thread visibility
            if (s == NSTG - 2) { asm volatile("cp.async.wait_group 0;\n"); }
            else               { asm volatile("cp.async.wait_group 1;\n"); }
            __syncthreads();   // also: all warps done reading stage s (slot s%3)
            if (s + 3 < NSTG) load_stage(s + 3);   // slot (s+3)%3 == s%3: safe
            ldsm_half(s + 1, 0, a0, b0);
        }
        mma_half(a1, b1);
    }

    // epilogue: tanh + weighted reduce over this CTA's 128 d-columns
    #pragma unroll
    for (int mi = 0; mi < 2; mi++) {
        float s0 = 0.f, s1 = 0.f;   // rows (lane>>2) and (lane>>2)+8
        #pragma unroll
        for (int j = 0; j < 8; j++) {
            int nc = wn + j*8 + 2*(lane & 3);
            float qb0 = qb_s[nc], qb1 = qb_s[nc+1];
            float w0 = ws_s[nc],  w1 = ws_s[nc+1];
            s0 += tanhf(acc[mi][j][0] + qb0)*w0 + tanhf(acc[mi][j][1] + qb1)*w1;
            s1 += tanhf(acc[mi][j][2] + qb0)*w0 + tanhf(acc[mi][j][3] + qb1)*w1;
        }
        s0 += __shfl_xor_sync(0xffffffffu, s0, 1);
        s0 += __shfl_xor_sync(0xffffffffu, s0, 2);
        s1 += __shfl_xor_sync(0xffffffffu, s1, 1);
        s1 += __shfl_xor_sync(0xffffffffu, s1, 2);
        if ((lane & 3) == 0) {
            int m0 = bm0 + wm + mi*16 + (lane >> 2);
            atomicAdd(&g_score[m0],     s0);
            atomicAdd(&g_score[m0 + 8], s1);
        }
    }
}

// ---------------- sigmoid + normalize -> attn (also zero context) ----------------
__global__ void normalize_kernel(const float* __restrict__ b_score, float* __restrict__ attn_out,
                                 int write_attn) {
    int b = blockIdx.x, t = threadIdx.x;     // 256 threads, 2048 elems
    __shared__ float red[256];
    for (int h = t; h < H_; h += 256) g_context[b*H_ + h] = 0.f;
    float bs = b_score[0];
    float sv[8];
    float local = 0.f;
    #pragma unroll
    for (int i = 0; i < 8; i++) {
        float x = g_score[b*VLEN_ + t + i*256] + bs;
        float s = 1.f / (1.f + __expf(-x));
        sv[i] = s; local += s;
    }
    red[t] = local; __syncthreads();
    #pragma unroll
    for (int o = 128; o; o >>= 1) { if (t < o) red[t] += red[t+o]; __syncthreads(); }
    float inv = 1.f / red[0];
    #pragma unroll
    for (int i = 0; i < 8; i++) {
        float a = sv[i] * inv;
        g_attn[b*VLEN_ + t + i*256] = a;
        if (write_attn) attn_out[b*VLEN_ + t + i*256] = a;
    }
}

// ------- context[b,h] = sum_v attn[b,v] * value[b,v,h]  (bf16 value from g_valcat) -------
__global__ void context_kernel() {
    int hc = blockIdx.x, b = blockIdx.y, vs = blockIdx.z;   // (4, B, 8)
    int h = hc*256 + threadIdx.x;
    __shared__ float a_s[256];
    a_s[threadIdx.x] = g_attn[b*VLEN_ + vs*256 + threadIdx.x];
    __syncthreads();
    const __nv_bfloat16* vp = g_valcat + ((size_t)b*VLEN_ + vs*256)*KC + h;
    float acc = 0.f;
    #pragma unroll 8
    for (int v = 0; v < 256; v++) acc += a_s[v] * __bfloat162float(vp[(size_t)v*KC]);
    atomicAdd(&g_context[b*H_ + h], acc);
}

// ---------------- output[b,h] = w_out[h] . [context | query] + b_out[h] ----------------
__global__ void output_kernel(const float* __restrict__ w_out, const float* __restrict__ b_out,
                              const float* __restrict__ query, float* __restrict__ out) {
    int b = blockIdx.y;
    int warp = threadIdx.x >> 5, lane = threadIdx.x & 31;
    int h = blockIdx.x*8 + warp;
    const float* wr = w_out + (size_t)h*(2*H_);
    const float* ctx = g_context + b*H_;
    const float* q = query + b*H_;
    float acc = 0.f;
    for (int k = lane; k < H_; k += 32) acc += wr[k]*ctx[k];
    for (int k = lane; k < H_; k += 32) acc += wr[H_+k]*q[k];
    #pragma unroll
    for (int o = 16; o; o >>= 1) acc += __shfl_xor_sync(0xffffffffu, acc, o);
    if (!lane) out[b*H_ + h] = acc + b_out[h];
}

// ---------------- launch ----------------
extern "C" void kernel_launch(void* const* d_in, const int* in_sizes, int n_in,
                              void* d_out, int out_size) {
    const float* query     = (const float*)d_in[0];
    const float* value     = (const float*)d_in[1];
    const float* prev_attn = (const float*)d_in[2];
    const float* conv_w    = (const float*)d_in[3];
    const float* conv_b    = (const float*)d_in[4];
    const float* w_loc     = (const float*)d_in[5];
    const float* w_q       = (const float*)d_in[6];
    const float* w_v       = (const float*)d_in[7];
    const float* bias      = (const float*)d_in[8];
    const float* w_score   = (const float*)d_in[9];
    const float* b_score   = (const float*)d_in[10];
    const float* w_out     = (const float*)d_in[11];
    const float* b_out     = (const float*)d_in[12];
    float* out = (float*)d_out;

    (void)in_sizes; (void)n_in;

    cudaFuncSetAttribute(gemm_score_kernel,
                         cudaFuncAttributeMaxDynamicSharedMemorySize, SMEM_TOTAL_GEMM);

    build_valcat<<< (M_*(KC/8))/256, 256 >>>(value, prev_attn, conv_w, conv_b);
    build_wcat<<< (DIM_*(KC/8) + 255)/256, 256 >>>(w_v, w_loc);
    qbias_kernel<<< dim3(DIM_/8, B_), 256 >>>(query, w_q, bias);
    gemm_score_kernel<<< dim3(DIM_/BN, M_/BM), 256, SMEM_TOTAL_GEMM >>>(w_score);

    int write_attn = (out_size >= B_*H_ + M_) ? 1 : 0;   // output first, then attn
    normalize_kernel<<< B_, 256 >>>(b_score, out + B_*H_, write_attn);
    context_kernel<<< dim3(H_/256, B_, VLEN_/256), 256 >>>();
    output_kernel<<< dim3(H_/8, B_), 256 >>>(w_out, b_out, query, out);
}

// round 12
// speedup vs baseline: 1.2211x; 1.0197x over previous
#include <cuda_runtime.h>
#include <cuda_bf16.h>
#include <cstdint>

#define B_    32
#define VLEN_ 2048
#define H_    1024
#define DIM_  1024
#define C_    32
#define KC    1088              // 1024 (value) + 32 (conv feat) + 32 zero pad
#define M_    (B_*VLEN_)        // 65536

// ---------------- scratch (device globals: no runtime allocation) ----------------
__device__ __nv_bfloat16 g_valcat[(size_t)M_*KC];    // [65536][1088] bf16  (~142 MB)
__device__ __nv_bfloat16 g_wcat[(size_t)DIM_*KC];    // [1024][1088] bf16
__device__ float g_qbias[B_*DIM_];                   // qp[b,d] + bias[d]
__device__ float g_score[M_];
__device__ float g_attn[M_];
__device__ float g_context[B_*H_];

__device__ __forceinline__ uint32_t smem_u32(const void* p){
    return (uint32_t)__cvta_generic_to_shared(p);
}

// -------- prep: A matrix = [value(bf16) | conv_feat(bf16) | 0]; also zeroes g_score --------
__global__ void build_valcat(const float* __restrict__ value,
                             const float* __restrict__ prev_attn,
                             const float* __restrict__ conv_w,
                             const float* __restrict__ conv_b) {
    int t = blockIdx.x*256 + threadIdx.x;               // one 16B chunk each
    const int CHUNKS = KC/8;                            // 136
    if (t < M_) g_score[t] = 0.f;                       // fused zero_score
    if (t >= M_*CHUNKS) return;
    int bv = t / CHUNKS, chunk = t % CHUNKS;
    __align__(16) __nv_bfloat16 o[8];
    if (chunk < 128) {
        const float4* s = reinterpret_cast<const float4*>(value + (size_t)bv*H_ + chunk*8);
        float4 x = s[0], y = s[1];
        o[0]=__float2bfloat16(x.x); o[1]=__float2bfloat16(x.y);
        o[2]=__float2bfloat16(x.z); o[3]=__float2bfloat16(x.w);
        o[4]=__float2bfloat16(y.x); o[5]=__float2bfloat16(y.y);
        o[6]=__float2bfloat16(y.z); o[7]=__float2bfloat16(y.w);
    } else if (chunk < 132) {
        int b = bv >> 11, v = bv & 2047;
        float pm = (v > 0)        ? prev_attn[b*VLEN_ + v - 1] : 0.f;
        float pc =                  prev_attn[b*VLEN_ + v];
        float pp = (v < VLEN_-1)  ? prev_attn[b*VLEN_ + v + 1] : 0.f;
        int c0 = (chunk-128)*8;
        #pragma unroll
        for (int j = 0; j < 8; j++) {
            int c = c0 + j;
            float cf = conv_w[c*3+0]*pm + conv_w[c*3+1]*pc + conv_w[c*3+2]*pp + conv_b[c];
            o[j] = __float2bfloat16(cf);
        }
    } else {
        #pragma unroll
        for (int j = 0; j < 8; j++) o[j] = __float2bfloat16(0.f);
    }
    *reinterpret_cast<uint4*>(g_valcat + (size_t)bv*KC + chunk*8) = *reinterpret_cast<uint4*>(o);
}

// ---------------- prep: B matrix = [w_v | w_loc | 0] ----------------
__global__ void build_wcat(const float* __restrict__ w_v, const float* __restrict__ w_loc) {
    int t = blockIdx.x*256 + threadIdx.x;
    const int CHUNKS = KC/8;
    if (t >= DIM_*CHUNKS) return;
    int d = t / CHUNKS, chunk = t % CHUNKS;
    __align__(16) __nv_bfloat16 o[8];
    if (chunk < 128) {
        const float* s = w_v + (size_t)d*H_ + chunk*8;
        #pragma unroll
        for (int j = 0; j < 8; j++) o[j] = __float2bfloat16(s[j]);
    } else if (chunk < 132) {
        const float* s = w_loc + (size_t)d*C_ + (chunk-128)*8;
        #pragma unroll
        for (int j = 0; j < 8; j++) o[j] = __float2bfloat16(s[j]);
    } else {
        #pragma unroll
        for (int j = 0; j < 8; j++) o[j] = __float2bfloat16(0.f);
    }
    *reinterpret_cast<uint4*>(g_wcat + (size_t)d*KC + chunk*8) = *reinterpret_cast<uint4*>(o);
}

// ---------------- prep: qbias[b,d] = query[b] . w_q[d] + bias[d] (fp32 exact) ----------------
__global__ void qbias_kernel(const float* __restrict__ query,
                             const float* __restrict__ w_q,
                             const float* __restrict__ bias) {
    int b = blockIdx.y;
    int warp = threadIdx.x >> 5, lane = threadIdx.x & 31;
    int d = blockIdx.x*8 + warp;
    const float* q = query + b*H_;
    const float* w = w_q + (size_t)d*H_;
    float acc = 0.f;
    for (int h = lane; h < H_; h += 32) acc += q[h]*w[h];
    #pragma unroll
    for (int o = 16; o; o >>= 1) acc += __shfl_xor_sync(0xffffffffu, acc, o);
    if (!lane) g_qbias[b*DIM_ + d] = acc + bias[d];
}

// ---------------- fused GEMM + tanh + score reduction (HMMA path) ----------------
// C[m,n] = sum_k A[m,k]*B[n,k] ; score[m] += sum_n tanh(C + qbias[b,n]) * w_score[n]
// BM=128, BN=128; 4 warps (2x2), WARP TILE 64x64 (128 acc regs, 256-reg budget
// at 128 thr/CTA, 2 CTA/SM). LDSM traffic per stage: 128KB (was 192KB) ->
// crossbar (1536 cyc) now BELOW the HMMA floor (2048 cyc).
// KTILE=64 stages, STG=3, one wait+barrier per stage, ldsm/mma ping-pong.
#define BM 128
#define BN 128
#define KTILE 64
#define NSTG  (KC/KTILE)   // 17
#define STG 3
#define KPAD 72            // 64 + 8 pad (144B rows -> conflict-free ldmatrix)

#define A_STG_ELEMS (BM*KPAD)            // 9216
#define B_STG_ELEMS (BN*KPAD)            // 9216
#define SM_A_OFF 0
#define SM_B_OFF (STG*A_STG_ELEMS*2)                    // 55296
#define SM_QB_OFF (SM_B_OFF + STG*B_STG_ELEMS*2)        // 110592
#define SM_WS_OFF (SM_QB_OFF + BN*4)
#define SMEM_TOTAL_GEMM (SM_WS_OFF + BN*4)              // 111616

__device__ __forceinline__ void mma16816(float* c, const uint32_t* a, uint32_t b0, uint32_t b1) {
    asm("mma.sync.aligned.m16n8k16.row.col.f32.bf16.bf16.f32 "
        "{%0,%1,%2,%3}, {%4,%5,%6,%7}, {%8,%9}, {%0,%1,%2,%3};"
        : "+f"(c[0]), "+f"(c[1]), "+f"(c[2]), "+f"(c[3])
        : "r"(a[0]), "r"(a[1]), "r"(a[2]), "r"(a[3]), "r"(b0), "r"(b1));
}

__global__ __launch_bounds__(128, 2)
void gemm_score_kernel(const float* __restrict__ w_score) {
    extern __shared__ __align__(16) char sm[];
    __nv_bfloat16* As = reinterpret_cast<__nv_bfloat16*>(sm + SM_A_OFF);  // [STG][BM][KPAD]
    __nv_bfloat16* Bs = reinterpret_cast<__nv_bfloat16*>(sm + SM_B_OFF);  // [STG][BN][KPAD]
    float* qb_s = reinterpret_cast<float*>(sm + SM_QB_OFF);
    float* ws_s = reinterpret_cast<float*>(sm + SM_WS_OFF);

    const int t = threadIdx.x;         // 0..127
    const int warp = t >> 5, lane = t & 31;
    const int bn0 = blockIdx.x * BN;   // x fastest -> n-CTAs of one m-block co-resident
    const int bm0 = blockIdx.y * BM;
    const int batch = bm0 >> 11;       // 2048 rows per batch; BM | 2048

    qb_s[t] = g_qbias[batch*DIM_ + bn0 + t];       // t covers 0..127 = BN
    ws_s[t] = w_score[bn0 + t];

    // stage loader: 128 rows x 8 chunks(16B) per matrix; 128 thr -> 8+8 chunks each
    const int lrow = t >> 3;      // 0..15
    const int lch  = t & 7;       // 16B chunk within 128B row
    const __nv_bfloat16* Ag = g_valcat + (size_t)bm0*KC + lch*8;
    const __nv_bfloat16* Bg = g_wcat   + (size_t)bn0*KC + lch*8;

    const int wm = (warp >> 1) * 64;   // 2 warps along M
    const int wn = (warp & 1) * 64;    // 2 warps along N
    const int g = lane >> 3, idx = lane & 7;
    const int a_row0 = wm + idx + 8*(g & 1);      // + mi*16
    const int a_col0 = 8*(g >> 1);                // + kb
    const int b_row0 = wn + idx + 8*(g >> 1);     // + ni*16
    const int b_col0 = 8*(g & 1);                 // + kb

    float acc[4][8][4];                // 128 regs: mi 0..3 (m16), col-frag j 0..7
    #pragma unroll
    for (int i = 0; i < 4; i++)
        #pragma unroll
        for (int j = 0; j < 8; j++)
            #pragma unroll
            for (int k = 0; k < 4; k++) acc[i][j][k] = 0.f;

    auto load_stage = [&](int s) {
        int slot = s % STG;
        int k0 = s * KTILE;
        __nv_bfloat16* Ad = As + slot*A_STG_ELEMS;
        __nv_bfloat16* Bd = Bs + slot*B_STG_ELEMS;
        #pragma unroll
        for (int i = 0; i < 8; i++) {
            int r = lrow + i*16;
            uint32_t d = smem_u32(Ad + r*KPAD + lch*8);
            asm volatile("cp.async.cg.shared.global [%0], [%1], 16;\n"
                         :: "r"(d), "l"(Ag + (size_t)r*KC + k0));
            uint32_t db = smem_u32(Bd + r*KPAD + lch*8);
            asm volatile("cp.async.cg.shared.global [%0], [%1], 16;\n"
                         :: "r"(db), "l"(Bg + (size_t)r*KC + k0));
        }
        asm volatile("cp.async.commit_group;\n");
    };

    // load one kk-half's fragments (8 ldmatrix.x4); kb in {0,16,32,48}
    auto ldsm_half = [&](int s, int kb, uint32_t a[4][4], uint32_t bf[4][4]) {
        const __nv_bfloat16* Asl = As + (s % STG)*A_STG_ELEMS;
        const __nv_bfloat16* Bsl = Bs + (s % STG)*B_STG_ELEMS;
        #pragma unroll
        for (int mi = 0; mi < 4; mi++) {
            uint32_t addr = smem_u32(Asl + (a_row0 + mi*16)*KPAD + a_col0 + kb);
            asm volatile("ldmatrix.sync.aligned.m8n8.x4.shared.b16 {%0,%1,%2,%3}, [%4];"
                         : "=r"(a[mi][0]), "=r"(a[mi][1]), "=r"(a[mi][2]), "=r"(a[mi][3])
                         : "r"(addr));
        }
        #pragma unroll
        for (int ni = 0; ni < 4; ni++) {
            uint32_t addr = smem_u32(Bsl + (b_row0 + ni*16)*KPAD + b_col0 + kb);
            asm volatile("ldmatrix.sync.aligned.m8n8.x4.shared.b16 {%0,%1,%2,%3}, [%4];"
                         : "=r"(bf[ni][0]), "=r"(bf[ni][1]), "=r"(bf[ni][2]), "=r"(bf[ni][3])
                         : "r"(addr));
        }
    };

    auto mma_half = [&](uint32_t a[4][4], uint32_t bf[4][4]) {
        #pragma unroll
        for (int mi = 0; mi < 4; mi++)
            #pragma unroll
            for (int ni = 0; ni < 4; ni++) {
                mma16816(acc[mi][ni*2+0], a[mi], bf[ni][0], bf[ni][1]);
                mma16816(acc[mi][ni*2+1], a[mi], bf[ni][2], bf[ni][3]);
            }
    };

    uint32_t a0[4][4], b0[4][4], a1[4][4], b1[4][4];

    // prologue: 3 groups in flight; stage 0 landed before first ldsm
    load_stage(0); load_stage(1); load_stage(2);
    asm volatile("cp.async.wait_group 2;\n");
    __syncthreads();
    ldsm_half(0, 0, a0, b0);

    for (int s = 0; s < NSTG; ++s) {
        // 4 kk-halves of ping-pong, no barriers inside
        ldsm_half(s, 16, a1, b1);  mma_half(a0, b0);
        ldsm_half(s, 32, a0, b0);  mma_half(a1, b1);
        ldsm_half(s, 48, a1, b1);  mma_half(a0, b0);
        if (s + 1 < NSTG) {
            // stage s+1 landed (own groups), then cross-thread visibility
            if (s == NSTG - 2) { asm volatile("cp.async.wait_group 0;\n"); }
            else               { asm volatile("cp.async.wait_group 1;\n"); }
            __syncthreads();   // also: all warps done reading stage s (slot s%3)
            if (s + 3 < NSTG) load_stage(s + 3);   // slot (s+3)%3 == s%3: safe
            ldsm_half(s + 1, 0, a0, b0);
        }
        mma_half(a1, b1);
    }

    // epilogue: tanh + weighted reduce over this CTA's 128 d-columns
    #pragma unroll
    for (int mi = 0; mi < 4; mi++) {
        float s0 = 0.f, s1 = 0.f;   // rows (lane>>2) and (lane>>2)+8
        #pragma unroll
        for (int j = 0; j < 8; j++) {
            int nc = wn + j*8 + 2*(lane & 3);
            float qb0 = qb_s[nc], qb1 = qb_s[nc+1];
            float w0 = ws_s[nc],  w1 = ws_s[nc+1];
            s0 += tanhf(acc[mi][j][0] + qb0)*w0 + tanhf(acc[mi][j][1] + qb1)*w1;
            s1 += tanhf(acc[mi][j][2] + qb0)*w0 + tanhf(acc[mi][j][3] + qb1)*w1;
        }
        s0 += __shfl_xor_sync(0xffffffffu, s0, 1);
        s0 += __shfl_xor_sync(0xffffffffu, s0, 2);
        s1 += __shfl_xor_sync(0xffffffffu, s1, 1);
        s1 += __shfl_xor_sync(0xffffffffu, s1, 2);
        if ((lane & 3) == 0) {
            int m0 = bm0 + wm + mi*16 + (lane >> 2);
            atomicAdd(&g_score[m0],     s0);
            atomicAdd(&g_score[m0 + 8], s1);
        }
    }
}

// ---------------- sigmoid + normalize -> attn (also zero context) ----------------
__global__ void normalize_kernel(const float* __restrict__ b_score, float* __restrict__ attn_out,
                                 int write_attn) {
    int b = blockIdx.x, t = threadIdx.x;     // 256 threads, 2048 elems
    __shared__ float red[256];
    for (int h = t; h < H_; h += 256) g_context[b*H_ + h] = 0.f;
    float bs = b_score[0];
    float sv[8];
    float local = 0.f;
    #pragma unroll
    for (int i = 0; i < 8; i++) {
        float x = g_score[b*VLEN_ + t + i*256] + bs;
        float s = 1.f / (1.f + __expf(-x));
        sv[i] = s; local += s;
    }
    red[t] = local; __syncthreads();
    #pragma unroll
    for (int o = 128; o; o >>= 1) { if (t < o) red[t] += red[t+o]; __syncthreads(); }
    float inv = 1.f / red[0];
    #pragma unroll
    for (int i = 0; i < 8; i++) {
        float a = sv[i] * inv;
        g_attn[b*VLEN_ + t + i*256] = a;
        if (write_attn) attn_out[b*VLEN_ + t + i*256] = a;
    }
}

// ------- context[b,h] = sum_v attn[b,v] * value[b,v,h]  (bf16 value from g_valcat) -------
__global__ void context_kernel() {
    int hc = blockIdx.x, b = blockIdx.y, vs = blockIdx.z;   // (4, B, 8)
    int h = hc*256 + threadIdx.x;
    __shared__ float a_s[256];
    a_s[threadIdx.x] = g_attn[b*VLEN_ + vs*256 + threadIdx.x];
    __syncthreads();
    const __nv_bfloat16* vp = g_valcat + ((size_t)b*VLEN_ + vs*256)*KC + h;
    float acc = 0.f;
    #pragma unroll 8
    for (int v = 0; v < 256; v++) acc += a_s[v] * __bfloat162float(vp[(size_t)v*KC]);
    atomicAdd(&g_context[b*H_ + h], acc);
}

// ---------------- output[b,h] = w_out[h] . [context | query] + b_out[h] ----------------
__global__ void output_kernel(const float* __restrict__ w_out, const float* __restrict__ b_out,
                              const float* __restrict__ query, float* __restrict__ out) {
    int b = blockIdx.y;
    int warp = threadIdx.x >> 5, lane = threadIdx.x & 31;
    int h = blockIdx.x*8 + warp;
    const float* wr = w_out + (size_t)h*(2*H_);
    const float* ctx = g_context + b*H_;
    const float* q = query + b*H_;
    float acc = 0.f;
    for (int k = lane; k < H_; k += 32) acc += wr[k]*ctx[k];
    for (int k = lane; k < H_; k += 32) acc += wr[H_+k]*q[k];
    #pragma unroll
    for (int o = 16; o; o >>= 1) acc += __shfl_xor_sync(0xffffffffu, acc, o);
    if (!lane) out[b*H_ + h] = acc + b_out[h];
}

// ---------------- launch ----------------
extern "C" void kernel_launch(void* const* d_in, const int* in_sizes, int n_in,
                              void* d_out, int out_size) {
    const float* query     = (const float*)d_in[0];
    const float* value     = (const float*)d_in[1];
    const float* prev_attn = (const float*)d_in[2];
    const float* conv_w    = (const float*)d_in[3];
    const float* conv_b    = (const float*)d_in[4];
    const float* w_loc     = (const float*)d_in[5];
    const float* w_q       = (const float*)d_in[6];
    const float* w_v       = (const float*)d_in[7];
    const float* bias      = (const float*)d_in[8];
    const float* w_score   = (const float*)d_in[9];
    const float* b_score   = (const float*)d_in[10];
    const float* w_out     = (const float*)d_in[11];
    const float* b_out     = (const float*)d_in[12];
    float* out = (float*)d_out;

    (void)in_sizes; (void)n_in;

    cudaFuncSetAttribute(gemm_score_kernel,
                         cudaFuncAttributeMaxDynamicSharedMemorySize, SMEM_TOTAL_GEMM);

    build_valcat<<< (M_*(KC/8))/256, 256 >>>(value, prev_attn, conv_w, conv_b);
    build_wcat<<< (DIM_*(KC/8) + 255)/256, 256 >>>(w_v, w_loc);
    qbias_kernel<<< dim3(DIM_/8, B_), 256 >>>(query, w_q, bias);
    gemm_score_kernel<<< dim3(DIM_/BN, M_/BM), 128, SMEM_TOTAL_GEMM >>>(w_score);

    int write_attn = (out_size >= B_*H_ + M_) ? 1 : 0;   // output first, then attn
    normalize_kernel<<< B_, 256 >>>(b_score, out + B_*H_, write_attn);
    context_kernel<<< dim3(H_/256, B_, VLEN_/256), 256 >>>();
    output_kernel<<< dim3(H_/8, B_), 256 >>>(w_out, b_out, query, out);
}

// round 13
// speedup vs baseline: 1.3260x; 1.0859x over previous
#include <cuda_runtime.h>
#include <cuda_bf16.h>
#include <cstdint>

#define B_    32
#define VLEN_ 2048
#define H_    1024
#define DIM_  1024
#define C_    32
#define KC    1088              // 1024 (value) + 32 (conv feat) + 32 zero pad
#define M_    (B_*VLEN_)        // 65536

// ---------------- scratch (device globals: no runtime allocation) ----------------
__device__ __nv_bfloat16 g_valcat[(size_t)M_*KC];    // [65536][1088] bf16  (~142 MB)
__device__ __nv_bfloat16 g_wcat[(size_t)DIM_*KC];    // [1024][1088] bf16
__device__ float g_qbias[B_*DIM_];                   // qp[b,d] + bias[d]
__device__ float g_score[M_];
__device__ float g_attn[M_];
__device__ float g_context[B_*H_];

__device__ __forceinline__ uint32_t smem_u32(const void* p){
    return (uint32_t)__cvta_generic_to_shared(p);
}

#define MBARRIER_INIT(mbar, cnt) \
    asm volatile("mbarrier.init.shared.b64 [%0], %1;" :: "r"((uint32_t)(mbar)), "r"((uint32_t)(cnt)) : "memory")

#define MBARRIER_ARRIVE(mbar) \
    asm volatile("mbarrier.arrive.shared.b64 _, [%0];" :: "r"((uint32_t)(mbar)) : "memory")

#define MBARRIER_WAIT_PARITY(mbar_smem_addr, phase_parity) do { \
    uint32_t _mbar = (uint32_t)(mbar_smem_addr); \
    uint32_t _parity = (uint32_t)(phase_parity); \
    uint32_t _done; \
    asm volatile("{\n\t.reg .pred p;\n\t" \
        "mbarrier.try_wait.parity.acquire.cta.shared::cta.b64 p, [%1], %2;\n\t" \
        "selp.b32 %0, 1, 0, p;\n\t}" \
        : "=r"(_done) : "r"(_mbar), "r"(_parity) : "memory"); \
    if (!_done) { \
        asm volatile("{\n\t.reg .pred P1;\n\t" \
            "WAIT_LOOP_%=:\n\t" \
            "mbarrier.try_wait.parity.acquire.cta.shared::cta.b64 P1, [%0], %1, 0x989680;\n\t" \
            "@P1 bra.uni WAIT_DONE_%=;\n\t" \
            "bra.uni WAIT_LOOP_%=;\n\t" \
            "WAIT_DONE_%=:\n\t}" \
            :: "r"(_mbar), "r"(_parity) : "memory"); \
    } \
} while(0)

// -------- prep: A matrix = [value(bf16) | conv_feat(bf16) | 0]; also zeroes g_score --------
__global__ void build_valcat(const float* __restrict__ value,
                             const float* __restrict__ prev_attn,
                             const float* __restrict__ conv_w,
                             const float* __restrict__ conv_b) {
    int t = blockIdx.x*256 + threadIdx.x;               // one 16B chunk each
    const int CHUNKS = KC/8;                            // 136
    if (t < M_) g_score[t] = 0.f;                       // fused zero_score
    if (t >= M_*CHUNKS) return;
    int bv = t / CHUNKS, chunk = t % CHUNKS;
    __align__(16) __nv_bfloat16 o[8];
    if (chunk < 128) {
        const float4* s = reinterpret_cast<const float4*>(value + (size_t)bv*H_ + chunk*8);
        float4 x = s[0], y = s[1];
        o[0]=__float2bfloat16(x.x); o[1]=__float2bfloat16(x.y);
        o[2]=__float2bfloat16(x.z); o[3]=__float2bfloat16(x.w);
        o[4]=__float2bfloat16(y.x); o[5]=__float2bfloat16(y.y);
        o[6]=__float2bfloat16(y.z); o[7]=__float2bfloat16(y.w);
    } else if (chunk < 132) {
        int b = bv >> 11, v = bv & 2047;
        float pm = (v > 0)        ? prev_attn[b*VLEN_ + v - 1] : 0.f;
        float pc =                  prev_attn[b*VLEN_ + v];
        float pp = (v < VLEN_-1)  ? prev_attn[b*VLEN_ + v + 1] : 0.f;
        int c0 = (chunk-128)*8;
        #pragma unroll
        for (int j = 0; j < 8; j++) {
            int c = c0 + j;
            float cf = conv_w[c*3+0]*pm + conv_w[c*3+1]*pc + conv_w[c*3+2]*pp + conv_b[c];
            o[j] = __float2bfloat16(cf);
        }
    } else {
        #pragma unroll
        for (int j = 0; j < 8; j++) o[j] = __float2bfloat16(0.f);
    }
    *reinterpret_cast<uint4*>(g_valcat + (size_t)bv*KC + chunk*8) = *reinterpret_cast<uint4*>(o);
}

// ---------------- prep: B matrix = [w_v | w_loc | 0] ----------------
__global__ void build_wcat(const float* __restrict__ w_v, const float* __restrict__ w_loc) {
    int t = blockIdx.x*256 + threadIdx.x;
    const int CHUNKS = KC/8;
    if (t >= DIM_*CHUNKS) return;
    int d = t / CHUNKS, chunk = t % CHUNKS;
    __align__(16) __nv_bfloat16 o[8];
    if (chunk < 128) {
        const float* s = w_v + (size_t)d*H_ + chunk*8;
        #pragma unroll
        for (int j = 0; j < 8; j++) o[j] = __float2bfloat16(s[j]);
    } else if (chunk < 132) {
        const float* s = w_loc + (size_t)d*C_ + (chunk-128)*8;
        #pragma unroll
        for (int j = 0; j < 8; j++) o[j] = __float2bfloat16(s[j]);
    } else {
        #pragma unroll
        for (int j = 0; j < 8; j++) o[j] = __float2bfloat16(0.f);
    }
    *reinterpret_cast<uint4*>(g_wcat + (size_t)d*KC + chunk*8) = *reinterpret_cast<uint4*>(o);
}

// ---------------- prep: qbias[b,d] = query[b] . w_q[d] + bias[d] (fp32 exact) ----------------
__global__ void qbias_kernel(const float* __restrict__ query,
                             const float* __restrict__ w_q,
                             const float* __restrict__ bias) {
    int b = blockIdx.y;
    int warp = threadIdx.x >> 5, lane = threadIdx.x & 31;
    int d = blockIdx.x*8 + warp;
    const float* q = query + b*H_;
    const float* w = w_q + (size_t)d*H_;
    float acc = 0.f;
    for (int h = lane; h < H_; h += 32) acc += q[h]*w[h];
    #pragma unroll
    for (int o = 16; o; o >>= 1) acc += __shfl_xor_sync(0xffffffffu, acc, o);
    if (!lane) g_qbias[b*DIM_ + d] = acc + bias[d];
}

// ---------------- fused GEMM + tanh + score reduction (HMMA path) ----------------
// BM=128, BN=128; 4 warps (2x2), warp tile 64x64; KTILE=64, STG=3.
// mbarrier producer/consumer pipeline: NO per-stage __syncthreads.
// full[slot]: cp.async.mbarrier.arrive.noinc x128 ; empty[slot]: arrive x128
// after last ldsm of the slot. Acquire/release chain replaces the rendezvous;
// warps may skew by up to ~1 stage without stalling each other.
#define BM 128
#define BN 128
#define KTILE 64
#define NSTG  (KC/KTILE)   // 17
#define STG 3
#define KPAD 72            // 64 + 8 pad (144B rows -> conflict-free ldmatrix)

#define A_STG_ELEMS (BM*KPAD)            // 9216
#define B_STG_ELEMS (BN*KPAD)            // 9216
#define SM_A_OFF 0
#define SM_B_OFF (STG*A_STG_ELEMS*2)                    // 55296
#define SM_QB_OFF (SM_B_OFF + STG*B_STG_ELEMS*2)        // 110592
#define SM_WS_OFF (SM_QB_OFF + BN*4)
#define SM_MBAR_OFF (SM_WS_OFF + BN*4)                  // 6 x 8B mbarriers
#define SMEM_TOTAL_GEMM (SM_MBAR_OFF + 64)              // 111680

__device__ __forceinline__ void mma16816(float* c, const uint32_t* a, uint32_t b0, uint32_t b1) {
    asm("mma.sync.aligned.m16n8k16.row.col.f32.bf16.bf16.f32 "
        "{%0,%1,%2,%3}, {%4,%5,%6,%7}, {%8,%9}, {%0,%1,%2,%3};"
        : "+f"(c[0]), "+f"(c[1]), "+f"(c[2]), "+f"(c[3])
        : "r"(a[0]), "r"(a[1]), "r"(a[2]), "r"(a[3]), "r"(b0), "r"(b1));
}

__global__ __launch_bounds__(128, 2)
void gemm_score_kernel(const float* __restrict__ w_score) {
    extern __shared__ __align__(16) char sm[];
    __nv_bfloat16* As = reinterpret_cast<__nv_bfloat16*>(sm + SM_A_OFF);  // [STG][BM][KPAD]
    __nv_bfloat16* Bs = reinterpret_cast<__nv_bfloat16*>(sm + SM_B_OFF);  // [STG][BN][KPAD]
    float* qb_s = reinterpret_cast<float*>(sm + SM_QB_OFF);
    float* ws_s = reinterpret_cast<float*>(sm + SM_WS_OFF);
    const uint32_t mb_full  = smem_u32(sm + SM_MBAR_OFF);        // +8*slot
    const uint32_t mb_empty = mb_full + 24;                      // +8*slot

    const int t = threadIdx.x;         // 0..127
    const int warp = t >> 5, lane = t & 31;
    const int bn0 = blockIdx.x * BN;   // x fastest -> n-CTAs of one m-block co-resident
    const int bm0 = blockIdx.y * BM;
    const int batch = bm0 >> 11;       // 2048 rows per batch; BM | 2048

    qb_s[t] = g_qbias[batch*DIM_ + bn0 + t];       // t covers 0..127 = BN
    ws_s[t] = w_score[bn0 + t];

    if (t == 0) {
        #pragma unroll
        for (int i = 0; i < STG; i++) {
            MBARRIER_INIT(mb_full  + 8*i, 128);
            MBARRIER_INIT(mb_empty + 8*i, 128);
        }
    }
    __syncthreads();   // qb_s/ws_s visible; mbarriers initialized before any arrive

    // stage loader: 128 rows x 8 chunks(16B) per matrix; 128 thr -> 8+8 chunks each
    const int lrow = t >> 3;      // 0..15
    const int lch  = t & 7;       // 16B chunk within 128B row
    const __nv_bfloat16* Ag = g_valcat + (size_t)bm0*KC + lch*8;
    const __nv_bfloat16* Bg = g_wcat   + (size_t)bn0*KC + lch*8;

    const int wm = (warp >> 1) * 64;   // 2 warps along M
    const int wn = (warp & 1) * 64;    // 2 warps along N
    const int g = lane >> 3, idx = lane & 7;
    const int a_row0 = wm + idx + 8*(g & 1);      // + mi*16
    const int a_col0 = 8*(g >> 1);                // + kb
    const int b_row0 = wn + idx + 8*(g >> 1);     // + ni*16
    const int b_col0 = 8*(g & 1);                 // + kb

    float acc[4][8][4];                // 128 regs
    #pragma unroll
    for (int i = 0; i < 4; i++)
        #pragma unroll
        for (int j = 0; j < 8; j++)
            #pragma unroll
            for (int k = 0; k < 4; k++) acc[i][j][k] = 0.f;

    auto load_stage = [&](int s) {
        int slot = s % STG;
        int k0 = s * KTILE;
        __nv_bfloat16* Ad = As + slot*A_STG_ELEMS;
        __nv_bfloat16* Bd = Bs + slot*B_STG_ELEMS;
        #pragma unroll
        for (int i = 0; i < 8; i++) {
            int r = lrow + i*16;
            uint32_t d = smem_u32(Ad + r*KPAD + lch*8);
            asm volatile("cp.async.cg.shared.global [%0], [%1], 16;\n"
                         :: "r"(d), "l"(Ag + (size_t)r*KC + k0));
            uint32_t db = smem_u32(Bd + r*KPAD + lch*8);
            asm volatile("cp.async.cg.shared.global [%0], [%1], 16;\n"
                         :: "r"(db), "l"(Bg + (size_t)r*KC + k0));
        }
        // this thread arrives on full[slot] when ALL its prior cp.asyncs land
        asm volatile("cp.async.mbarrier.arrive.noinc.shared::cta.b64 [%0];\n"
                     :: "r"(mb_full + 8*slot) : "memory");
    };

    // load one kk-half's fragments (8 ldmatrix.x4); kb in {0,16,32,48}
    auto ldsm_half = [&](int s, int kb, uint32_t a[4][4], uint32_t bf[4][4]) {
        const __nv_bfloat16* Asl = As + (s % STG)*A_STG_ELEMS;
        const __nv_bfloat16* Bsl = Bs + (s % STG)*B_STG_ELEMS;
        #pragma unroll
        for (int mi = 0; mi < 4; mi++) {
            uint32_t addr = smem_u32(Asl + (a_row0 + mi*16)*KPAD + a_col0 + kb);
            asm volatile("ldmatrix.sync.aligned.m8n8.x4.shared.b16 {%0,%1,%2,%3}, [%4];"
                         : "=r"(a[mi][0]), "=r"(a[mi][1]), "=r"(a[mi][2]), "=r"(a[mi][3])
                         : "r"(addr));
        }
        #pragma unroll
        for (int ni = 0; ni < 4; ni++) {
            uint32_t addr = smem_u32(Bsl + (b_row0 + ni*16)*KPAD + b_col0 + kb);
            asm volatile("ldmatrix.sync.aligned.m8n8.x4.shared.b16 {%0,%1,%2,%3}, [%4];"
                         : "=r"(bf[ni][0]), "=r"(bf[ni][1]), "=r"(bf[ni][2]), "=r"(bf[ni][3])
                         : "r"(addr));
        }
    };

    auto mma_half = [&](uint32_t a[4][4], uint32_t bf[4][4]) {
        #pragma unroll
        for (int mi = 0; mi < 4; mi++)
            #pragma unroll
            for (int ni = 0; ni < 4; ni++) {
                mma16816(acc[mi][ni*2+0], a[mi], bf[ni][0], bf[ni][1]);
                mma16816(acc[mi][ni*2+1], a[mi], bf[ni][2], bf[ni][3]);
            }
    };

    uint32_t a0[4][4], b0[4][4], a1[4][4], b1[4][4];

    // prologue: fill all 3 slots; wait stage 0 (full[0] phase 0)
    load_stage(0); load_stage(1); load_stage(2);
    MBARRIER_WAIT_PARITY(mb_full + 0, 0);
    ldsm_half(0, 0, a0, b0);

    for (int s = 0; s < NSTG; ++s) {
        int slot = s % STG;
        // 4 kk-halves of ping-pong
        ldsm_half(s, 16, a1, b1);  mma_half(a0, b0);
        ldsm_half(s, 32, a0, b0);  mma_half(a1, b1);
        ldsm_half(s, 48, a1, b1);  mma_half(a0, b0);
        MBARRIER_ARRIVE(mb_empty + 8*slot);         // done reading slot s%3 (release)
        if (s + 1 < NSTG) {
            MBARRIER_WAIT_PARITY(mb_full + 8*((s+1)%STG), ((s+1)/STG)&1);
            ldsm_half(s + 1, 0, a0, b0);
        }
        mma_half(a1, b1);
        if (s + 3 < NSTG) {
            // slot s%3 reused by stage s+3: wait consumers of round s/3 (acquire)
            MBARRIER_WAIT_PARITY(mb_empty + 8*slot, (s/STG)&1);
            load_stage(s + 3);
        }
    }

    // epilogue: tanh + weighted reduce over this CTA's 128 d-columns
    #pragma unroll
    for (int mi = 0; mi < 4; mi++) {
        float s0 = 0.f, s1 = 0.f;   // rows (lane>>2) and (lane>>2)+8
        #pragma unroll
        for (int j = 0; j < 8; j++) {
            int nc = wn + j*8 + 2*(lane & 3);
            float qb0 = qb_s[nc], qb1 = qb_s[nc+1];
            float w0 = ws_s[nc],  w1 = ws_s[nc+1];
            s0 += tanhf(acc[mi][j][0] + qb0)*w0 + tanhf(acc[mi][j][1] + qb1)*w1;
            s1 += tanhf(acc[mi][j][2] + qb0)*w0 + tanhf(acc[mi][j][3] + qb1)*w1;
        }
        s0 += __shfl_xor_sync(0xffffffffu, s0, 1);
        s0 += __shfl_xor_sync(0xffffffffu, s0, 2);
        s1 += __shfl_xor_sync(0xffffffffu, s1, 1);
        s1 += __shfl_xor_sync(0xffffffffu, s1, 2);
        if ((lane & 3) == 0) {
            int m0 = bm0 + wm + mi*16 + (lane >> 2);
            atomicAdd(&g_score[m0],     s0);
            atomicAdd(&g_score[m0 + 8], s1);
        }
    }
}

// ---------------- sigmoid + normalize -> attn (also zero context) ----------------
__global__ void normalize_kernel(const float* __restrict__ b_score, float* __restrict__ attn_out,
                                 int write_attn) {
    int b = blockIdx.x, t = threadIdx.x;     // 256 threads, 2048 elems
    __shared__ float red[256];
    for (int h = t; h < H_; h += 256) g_context[b*H_ + h] = 0.f;
    float bs = b_score[0];
    float sv[8];
    float local = 0.f;
    #pragma unroll
    for (int i = 0; i < 8; i++) {
        float x = g_score[b*VLEN_ + t + i*256] + bs;
        float s = 1.f / (1.f + __expf(-x));
        sv[i] = s; local += s;
    }
    red[t] = local; __syncthreads();
    #pragma unroll
    for (int o = 128; o; o >>= 1) { if (t < o) red[t] += red[t+o]; __syncthreads(); }
    float inv = 1.f / red[0];
    #pragma unroll
    for (int i = 0; i < 8; i++) {
        float a = sv[i] * inv;
        g_attn[b*VLEN_ + t + i*256] = a;
        if (write_attn) attn_out[b*VLEN_ + t + i*256] = a;
    }
}

// ------- context[b,h] = sum_v attn[b,v] * value[b,v,h]  (bf16 value from g_valcat) -------
__global__ void context_kernel() {
    int hc = blockIdx.x, b = blockIdx.y, vs = blockIdx.z;   // (4, B, 8)
    int h = hc*256 + threadIdx.x;
    __shared__ float a_s[256];
    a_s[threadIdx.x] = g_attn[b*VLEN_ + vs*256 + threadIdx.x];
    __syncthreads();
    const __nv_bfloat16* vp = g_valcat + ((size_t)b*VLEN_ + vs*256)*KC + h;
    float acc = 0.f;
    #pragma unroll 8
    for (int v = 0; v < 256; v++) acc += a_s[v] * __bfloat162float(vp[(size_t)v*KC]);
    atomicAdd(&g_context[b*H_ + h], acc);
}

// ---------------- output[b,h] = w_out[h] . [context | query] + b_out[h] ----------------
__global__ void output_kernel(const float* __restrict__ w_out, const float* __restrict__ b_out,
                              const float* __restrict__ query, float* __restrict__ out) {
    int b = blockIdx.y;
    int warp = threadIdx.x >> 5, lane = threadIdx.x & 31;
    int h = blockIdx.x*8 + warp;
    const float* wr = w_out + (size_t)h*(2*H_);
    const float* ctx = g_context + b*H_;
    const float* q = query + b*H_;
    float acc = 0.f;
    for (int k = lane; k < H_; k += 32) acc += wr[k]*ctx[k];
    for (int k = lane; k < H_; k += 32) acc += wr[H_+k]*q[k];
    #pragma unroll
    for (int o = 16; o; o >>= 1) acc += __shfl_xor_sync(0xffffffffu, acc, o);
    if (!lane) out[b*H_ + h] = acc + b_out[h];
}

// ---------------- launch ----------------
extern "C" void kernel_launch(void* const* d_in, const int* in_sizes, int n_in,
                              void* d_out, int out_size) {
    const float* query     = (const float*)d_in[0];
    const float* value     = (const float*)d_in[1];
    const float* prev_attn = (const float*)d_in[2];
    const float* conv_w    = (const float*)d_in[3];
    const float* conv_b    = (const float*)d_in[4];
    const float* w_loc     = (const float*)d_in[5];
    const float* w_q       = (const float*)d_in[6];
    const float* w_v       = (const float*)d_in[7];
    const float* bias      = (const float*)d_in[8];
    const float* w_score   = (const float*)d_in[9];
    const float* b_score   = (const float*)d_in[10];
    const float* w_out     = (const float*)d_in[11];
    const float* b_out     = (const float*)d_in[12];
    float* out = (float*)d_out;

    (void)in_sizes; (void)n_in;

    cudaFuncSetAttribute(gemm_score_kernel,
                         cudaFuncAttributeMaxDynamicSharedMemorySize, SMEM_TOTAL_GEMM);

    build_valcat<<< (M_*(KC/8))/256, 256 >>>(value, prev_attn, conv_w, conv_b);
    build_wcat<<< (DIM_*(KC/8) + 255)/256, 256 >>>(w_v, w_loc);
    qbias_kernel<<< dim3(DIM_/8, B_), 256 >>>(query, w_q, bias);
    gemm_score_kernel<<< dim3(DIM_/BN, M_/BM), 128, SMEM_TOTAL_GEMM >>>(w_score);

    int write_attn = (out_size >= B_*H_ + M_) ? 1 : 0;   // output first, then attn
    normalize_kernel<<< B_, 256 >>>(b_score, out + B_*H_, write_attn);
    context_kernel<<< dim3(H_/256, B_, VLEN_/256), 256 >>>();
    output_kernel<<< dim3(H_/8, B_), 256 >>>(w_out, b_out, query, out);
}

// round 14
// speedup vs baseline: 1.3652x; 1.0295x over previous
#include <cuda_runtime.h>
#include <cuda_bf16.h>
#include <cstdint>

#define B_    32
#define VLEN_ 2048
#define H_    1024
#define DIM_  1024
#define C_    32
#define KC    1088              // 1024 (value) + 32 (conv feat) + 32 zero pad
#define M_    (B_*VLEN_)        // 65536

// ---------------- scratch (device globals: no runtime allocation) ----------------
__device__ __nv_bfloat16 g_valcat[(size_t)M_*KC];    // [65536][1088] bf16  (~142 MB)
__device__ __nv_bfloat16 g_wcat[(size_t)DIM_*KC];    // [1024][1088] bf16
__device__ float g_qbias[B_*DIM_];                   // qp[b,d] + bias[d]
__device__ float g_score[M_];
__device__ float g_attn[M_];
__device__ float g_context[B_*H_];

__device__ __forceinline__ uint32_t smem_u32(const void* p){
    return (uint32_t)__cvta_generic_to_shared(p);
}

#define MBARRIER_INIT(mbar, cnt) \
    asm volatile("mbarrier.init.shared.b64 [%0], %1;" :: "r"((uint32_t)(mbar)), "r"((uint32_t)(cnt)) : "memory")

#define MBARRIER_ARRIVE(mbar) \
    asm volatile("mbarrier.arrive.shared.b64 _, [%0];" :: "r"((uint32_t)(mbar)) : "memory")

#define MBARRIER_WAIT_PARITY(mbar_smem_addr, phase_parity) do { \
    uint32_t _mbar = (uint32_t)(mbar_smem_addr); \
    uint32_t _parity = (uint32_t)(phase_parity); \
    uint32_t _done; \
    asm volatile("{\n\t.reg .pred p;\n\t" \
        "mbarrier.try_wait.parity.acquire.cta.shared::cta.b64 p, [%1], %2;\n\t" \
        "selp.b32 %0, 1, 0, p;\n\t}" \
        : "=r"(_done) : "r"(_mbar), "r"(_parity) : "memory"); \
    if (!_done) { \
        asm volatile("{\n\t.reg .pred P1;\n\t" \
            "WAIT_LOOP_%=:\n\t" \
            "mbarrier.try_wait.parity.acquire.cta.shared::cta.b64 P1, [%0], %1, 0x989680;\n\t" \
            "@P1 bra.uni WAIT_DONE_%=;\n\t" \
            "bra.uni WAIT_LOOP_%=;\n\t" \
            "WAIT_DONE_%=:\n\t}" \
            :: "r"(_mbar), "r"(_parity) : "memory"); \
    } \
} while(0)

// ======== fused prep: valcat + wcat + qbias in ONE launch (blockIdx ranges) ========
#define VC_BLOCKS ((M_*(KC/8))/256)      // 34816
#define WC_BLOCKS ((DIM_*(KC/8))/256)    // 544
#define QB_BLOCKS ((DIM_/8)*B_)          // 4096
#define PREP_BLOCKS (VC_BLOCKS + WC_BLOCKS + QB_BLOCKS)

__global__ void prep_kernel(const float* __restrict__ value,
                            const float* __restrict__ prev_attn,
                            const float* __restrict__ conv_w,
                            const float* __restrict__ conv_b,
                            const float* __restrict__ w_v,
                            const float* __restrict__ w_loc,
                            const float* __restrict__ query,
                            const float* __restrict__ w_q,
                            const float* __restrict__ bias) {
    const int bid = blockIdx.x;
    const int CHUNKS = KC/8;                            // 136
    if (bid < VC_BLOCKS) {
        // ---- A matrix = [value(bf16) | conv_feat | 0]; also zeroes g_score ----
        int t = bid*256 + threadIdx.x;
        if (t < M_) g_score[t] = 0.f;
        int bv = t / CHUNKS, chunk = t % CHUNKS;
        __align__(16) __nv_bfloat16 o[8];
        if (chunk < 128) {
            const float4* s = reinterpret_cast<const float4*>(value + (size_t)bv*H_ + chunk*8);
            float4 x = s[0], y = s[1];
            o[0]=__float2bfloat16(x.x); o[1]=__float2bfloat16(x.y);
            o[2]=__float2bfloat16(x.z); o[3]=__float2bfloat16(x.w);
            o[4]=__float2bfloat16(y.x); o[5]=__float2bfloat16(y.y);
            o[6]=__float2bfloat16(y.z); o[7]=__float2bfloat16(y.w);
        } else if (chunk < 132) {
            int b = bv >> 11, v = bv & 2047;
            float pm = (v > 0)        ? prev_attn[b*VLEN_ + v - 1] : 0.f;
            float pc =                  prev_attn[b*VLEN_ + v];
            float pp = (v < VLEN_-1)  ? prev_attn[b*VLEN_ + v + 1] : 0.f;
            int c0 = (chunk-128)*8;
            #pragma unroll
            for (int j = 0; j < 8; j++) {
                int c = c0 + j;
                float cf = conv_w[c*3+0]*pm + conv_w[c*3+1]*pc + conv_w[c*3+2]*pp + conv_b[c];
                o[j] = __float2bfloat16(cf);
            }
        } else {
            #pragma unroll
            for (int j = 0; j < 8; j++) o[j] = __float2bfloat16(0.f);
        }
        *reinterpret_cast<uint4*>(g_valcat + (size_t)bv*KC + chunk*8) = *reinterpret_cast<uint4*>(o);
    } else if (bid < VC_BLOCKS + WC_BLOCKS) {
        // ---- B matrix = [w_v | w_loc | 0] ----
        int t = (bid - VC_BLOCKS)*256 + threadIdx.x;
        int d = t / CHUNKS, chunk = t % CHUNKS;
        __align__(16) __nv_bfloat16 o[8];
        if (chunk < 128) {
            const float* s = w_v + (size_t)d*H_ + chunk*8;
            #pragma unroll
            for (int j = 0; j < 8; j++) o[j] = __float2bfloat16(s[j]);
        } else if (chunk < 132) {
            const float* s = w_loc + (size_t)d*C_ + (chunk-128)*8;
            #pragma unroll
            for (int j = 0; j < 8; j++) o[j] = __float2bfloat16(s[j]);
        } else {
            #pragma unroll
            for (int j = 0; j < 8; j++) o[j] = __float2bfloat16(0.f);
        }
        *reinterpret_cast<uint4*>(g_wcat + (size_t)d*KC + chunk*8) = *reinterpret_cast<uint4*>(o);
    } else {
        // ---- qbias[b,d] = query[b].w_q[d] + bias[d] (fp32 exact) ----
        int blk = bid - VC_BLOCKS - WC_BLOCKS;      // 0..4095
        int warp = threadIdx.x >> 5, lane = threadIdx.x & 31;
        int b = blk >> 7;                           // /128
        int d = (blk & 127)*8 + warp;
        const float* q = query + b*H_;
        const float* w = w_q + (size_t)d*H_;
        float acc = 0.f;
        for (int h = lane; h < H_; h += 32) acc += q[h]*w[h];
        #pragma unroll
        for (int o = 16; o; o >>= 1) acc += __shfl_xor_sync(0xffffffffu, acc, o);
        if (!lane) g_qbias[b*DIM_ + d] = acc + bias[d];
    }
}

// ---------------- fused GEMM + tanh + score reduction (HMMA path) ----------------
// BM=128, BN=128; 4 warps (2x2), warp tile 64x64; KTILE=64, STG=3.
// mbarrier producer/consumer pipeline, no per-stage __syncthreads.
#define BM 128
#define BN 128
#define KTILE 64
#define NSTG  (KC/KTILE)   // 17
#define STG 3
#define KPAD 72            // 64 + 8 pad (144B rows -> conflict-free ldmatrix)

#define A_STG_ELEMS (BM*KPAD)            // 9216
#define B_STG_ELEMS (BN*KPAD)            // 9216
#define SM_A_OFF 0
#define SM_B_OFF (STG*A_STG_ELEMS*2)                    // 55296
#define SM_QB_OFF (SM_B_OFF + STG*B_STG_ELEMS*2)        // 110592
#define SM_WS_OFF (SM_QB_OFF + BN*4)
#define SM_MBAR_OFF (SM_WS_OFF + BN*4)                  // 6 x 8B mbarriers
#define SMEM_TOTAL_GEMM (SM_MBAR_OFF + 64)              // 111680

__device__ __forceinline__ void mma16816(float* c, const uint32_t* a, uint32_t b0, uint32_t b1) {
    asm("mma.sync.aligned.m16n8k16.row.col.f32.bf16.bf16.f32 "
        "{%0,%1,%2,%3}, {%4,%5,%6,%7}, {%8,%9}, {%0,%1,%2,%3};"
        : "+f"(c[0]), "+f"(c[1]), "+f"(c[2]), "+f"(c[3])
        : "r"(a[0]), "r"(a[1]), "r"(a[2]), "r"(a[3]), "r"(b0), "r"(b1));
}

__global__ __launch_bounds__(128, 2)
void gemm_score_kernel(const float* __restrict__ w_score) {
    extern __shared__ __align__(16) char sm[];
    __nv_bfloat16* As = reinterpret_cast<__nv_bfloat16*>(sm + SM_A_OFF);  // [STG][BM][KPAD]
    __nv_bfloat16* Bs = reinterpret_cast<__nv_bfloat16*>(sm + SM_B_OFF);  // [STG][BN][KPAD]
    float* qb_s = reinterpret_cast<float*>(sm + SM_QB_OFF);
    float* ws_s = reinterpret_cast<float*>(sm + SM_WS_OFF);
    const uint32_t mb_full  = smem_u32(sm + SM_MBAR_OFF);        // +8*slot
    const uint32_t mb_empty = mb_full + 24;                      // +8*slot

    const int t = threadIdx.x;         // 0..127
    const int warp = t >> 5, lane = t & 31;
    const int bn0 = blockIdx.x * BN;   // x fastest -> n-CTAs of one m-block co-resident
    const int bm0 = blockIdx.y * BM;
    const int batch = bm0 >> 11;       // 2048 rows per batch; BM | 2048

    qb_s[t] = g_qbias[batch*DIM_ + bn0 + t];       // t covers 0..127 = BN
    ws_s[t] = w_score[bn0 + t];

    if (t == 0) {
        #pragma unroll
        for (int i = 0; i < STG; i++) {
            MBARRIER_INIT(mb_full  + 8*i, 128);
            MBARRIER_INIT(mb_empty + 8*i, 128);
        }
    }
    __syncthreads();   // qb_s/ws_s visible; mbarriers initialized before any arrive

    // stage loader: 128 rows x 8 chunks(16B) per matrix; 128 thr -> 8+8 chunks each
    const int lrow = t >> 3;      // 0..15
    const int lch  = t & 7;       // 16B chunk within 128B row
    const __nv_bfloat16* Ag = g_valcat + (size_t)bm0*KC + lch*8;
    const __nv_bfloat16* Bg = g_wcat   + (size_t)bn0*KC + lch*8;

    const int wm = (warp >> 1) * 64;   // 2 warps along M
    const int wn = (warp & 1) * 64;    // 2 warps along N
    const int g = lane >> 3, idx = lane & 7;
    const int a_row0 = wm + idx + 8*(g & 1);      // + mi*16
    const int a_col0 = 8*(g >> 1);                // + kb
    const int b_row0 = wn + idx + 8*(g >> 1);     // + ni*16
    const int b_col0 = 8*(g & 1);                 // + kb

    float acc[4][8][4];                // 128 regs
    #pragma unroll
    for (int i = 0; i < 4; i++)
        #pragma unroll
        for (int j = 0; j < 8; j++)
            #pragma unroll
            for (int k = 0; k < 4; k++) acc[i][j][k] = 0.f;

    auto load_stage = [&](int s) {
        int slot = s % STG;
        int k0 = s * KTILE;
        __nv_bfloat16* Ad = As + slot*A_STG_ELEMS;
        __nv_bfloat16* Bd = Bs + slot*B_STG_ELEMS;
        #pragma unroll
        for (int i = 0; i < 8; i++) {
            int r = lrow + i*16;
            uint32_t d = smem_u32(Ad + r*KPAD + lch*8);
            asm volatile("cp.async.cg.shared.global [%0], [%1], 16;\n"
                         :: "r"(d), "l"(Ag + (size_t)r*KC + k0));
            uint32_t db = smem_u32(Bd + r*KPAD + lch*8);
            asm volatile("cp.async.cg.shared.global [%0], [%1], 16;\n"
                         :: "r"(db), "l"(Bg + (size_t)r*KC + k0));
        }
        // this thread arrives on full[slot] when ALL its prior cp.asyncs land
        asm volatile("cp.async.mbarrier.arrive.noinc.shared::cta.b64 [%0];\n"
                     :: "r"(mb_full + 8*slot) : "memory");
    };

    // load one kk-half's fragments (8 ldmatrix.x4); kb in {0,16,32,48}
    auto ldsm_half = [&](int s, int kb, uint32_t a[4][4], uint32_t bf[4][4]) {
        const __nv_bfloat16* Asl = As + (s % STG)*A_STG_ELEMS;
        const __nv_bfloat16* Bsl = Bs + (s % STG)*B_STG_ELEMS;
        #pragma unroll
        for (int mi = 0; mi < 4; mi++) {
            uint32_t addr = smem_u32(Asl + (a_row0 + mi*16)*KPAD + a_col0 + kb);
            asm volatile("ldmatrix.sync.aligned.m8n8.x4.shared.b16 {%0,%1,%2,%3}, [%4];"
                         : "=r"(a[mi][0]), "=r"(a[mi][1]), "=r"(a[mi][2]), "=r"(a[mi][3])
                         : "r"(addr));
        }
        #pragma unroll
        for (int ni = 0; ni < 4; ni++) {
            uint32_t addr = smem_u32(Bsl + (b_row0 + ni*16)*KPAD + b_col0 + kb);
            asm volatile("ldmatrix.sync.aligned.m8n8.x4.shared.b16 {%0,%1,%2,%3}, [%4];"
                         : "=r"(bf[ni][0]), "=r"(bf[ni][1]), "=r"(bf[ni][2]), "=r"(bf[ni][3])
                         : "r"(addr));
        }
    };

    auto mma_half = [&](uint32_t a[4][4], uint32_t bf[4][4]) {
        #pragma unroll
        for (int mi = 0; mi < 4; mi++)
            #pragma unroll
            for (int ni = 0; ni < 4; ni++) {
                mma16816(acc[mi][ni*2+0], a[mi], bf[ni][0], bf[ni][1]);
                mma16816(acc[mi][ni*2+1], a[mi], bf[ni][2], bf[ni][3]);
            }
    };

    uint32_t a0[4][4], b0[4][4], a1[4][4], b1[4][4];

    // prologue: fill all 3 slots; wait stage 0 (full[0] phase 0)
    load_stage(0); load_stage(1); load_stage(2);
    MBARRIER_WAIT_PARITY(mb_full + 0, 0);
    ldsm_half(0, 0, a0, b0);

    for (int s = 0; s < NSTG; ++s) {
        int slot = s % STG;
        // 4 kk-halves of ping-pong
        ldsm_half(s, 16, a1, b1);  mma_half(a0, b0);
        ldsm_half(s, 32, a0, b0);  mma_half(a1, b1);
        ldsm_half(s, 48, a1, b1);
        MBARRIER_ARRIVE(mb_empty + 8*slot);   // last read of slot s done (release)
        mma_half(a0, b0);
        if (s + 1 < NSTG) {
            MBARRIER_WAIT_PARITY(mb_full + 8*((s+1)%STG), ((s+1)/STG)&1);
            ldsm_half(s + 1, 0, a0, b0);
        }
        mma_half(a1, b1);
        if (s + 3 < NSTG) {
            // slot s%3 reused by stage s+3: wait consumers of round s/3 (acquire)
            MBARRIER_WAIT_PARITY(mb_empty + 8*slot, (s/STG)&1);
            load_stage(s + 3);
        }
    }

    // epilogue: tanh + weighted reduce over this CTA's 128 d-columns
    #pragma unroll
    for (int mi = 0; mi < 4; mi++) {
        float s0 = 0.f, s1 = 0.f;   // rows (lane>>2) and (lane>>2)+8
        #pragma unroll
        for (int j = 0; j < 8; j++) {
            int nc = wn + j*8 + 2*(lane & 3);
            float qb0 = qb_s[nc], qb1 = qb_s[nc+1];
            float w0 = ws_s[nc],  w1 = ws_s[nc+1];
            s0 += tanhf(acc[mi][j][0] + qb0)*w0 + tanhf(acc[mi][j][1] + qb1)*w1;
            s1 += tanhf(acc[mi][j][2] + qb0)*w0 + tanhf(acc[mi][j][3] + qb1)*w1;
        }
        s0 += __shfl_xor_sync(0xffffffffu, s0, 1);
        s0 += __shfl_xor_sync(0xffffffffu, s0, 2);
        s1 += __shfl_xor_sync(0xffffffffu, s1, 1);
        s1 += __shfl_xor_sync(0xffffffffu, s1, 2);
        if ((lane & 3) == 0) {
            int m0 = bm0 + wm + mi*16 + (lane >> 2);
            atomicAdd(&g_score[m0],     s0);
            atomicAdd(&g_score[m0 + 8], s1);
        }
    }
}

// ---------------- sigmoid + normalize -> attn (also zero context) ----------------
__global__ void normalize_kernel(const float* __restrict__ b_score, float* __restrict__ attn_out,
                                 int write_attn) {
    int b = blockIdx.x, t = threadIdx.x;     // 256 threads, 2048 elems
    __shared__ float red[256];
    for (int h = t; h < H_; h += 256) g_context[b*H_ + h] = 0.f;
    float bs = b_score[0];
    float sv[8];
    float local = 0.f;
    #pragma unroll
    for (int i = 0; i < 8; i++) {
        float x = g_score[b*VLEN_ + t + i*256] + bs;
        float s = 1.f / (1.f + __expf(-x));
        sv[i] = s; local += s;
    }
    red[t] = local; __syncthreads();
    #pragma unroll
    for (int o = 128; o; o >>= 1) { if (t < o) red[t] += red[t+o]; __syncthreads(); }
    float inv = 1.f / red[0];
    #pragma unroll
    for (int i = 0; i < 8; i++) {
        float a = sv[i] * inv;
        g_attn[b*VLEN_ + t + i*256] = a;
        if (write_attn) attn_out[b*VLEN_ + t + i*256] = a;
    }
}

// ------- context[b,h] = sum_v attn[b,v]*value[b,v,h]  (bf16x2 from g_valcat) -------
__global__ void context_kernel() {
    int hc = blockIdx.x, b = blockIdx.y, vs = blockIdx.z;   // (2, B, 8)
    int h2 = hc*256 + threadIdx.x;       // bf16x2 index; h = 2*h2
    __shared__ float a_s[256];
    a_s[threadIdx.x] = g_attn[b*VLEN_ + vs*256 + threadIdx.x];
    __syncthreads();
    const uint32_t* vp = reinterpret_cast<const uint32_t*>(
        g_valcat + ((size_t)b*VLEN_ + vs*256)*KC) + h2;
    float acc0 = 0.f, acc1 = 0.f;
    #pragma unroll 8
    for (int v = 0; v < 256; v++) {
        uint32_t u = vp[(size_t)v*(KC/2)];
        __nv_bfloat162 p = *reinterpret_cast<__nv_bfloat162*>(&u);
        float av = a_s[v];
        acc0 += av * __bfloat162float(p.x);
        acc1 += av * __bfloat162float(p.y);
    }
    atomicAdd(&g_context[b*H_ + 2*h2],     acc0);
    atomicAdd(&g_context[b*H_ + 2*h2 + 1], acc1);
}

// ---------------- output[b,h] = w_out[h] . [context | query] + b_out[h] ----------------
__global__ void output_kernel(const float* __restrict__ w_out, const float* __restrict__ b_out,
                              const float* __restrict__ query, float* __restrict__ out) {
    int b = blockIdx.y;
    int warp = threadIdx.x >> 5, lane = threadIdx.x & 31;
    int h = blockIdx.x*8 + warp;
    const float* wr = w_out + (size_t)h*(2*H_);
    const float* ctx = g_context + b*H_;
    const float* q = query + b*H_;
    float acc = 0.f;
    for (int k = lane; k < H_; k += 32) acc += wr[k]*ctx[k];
    for (int k = lane; k < H_; k += 32) acc += wr[H_+k]*q[k];
    #pragma unroll
    for (int o = 16; o; o >>= 1) acc += __shfl_xor_sync(0xffffffffu, acc, o);
    if (!lane) out[b*H_ + h] = acc + b_out[h];
}

// ---------------- launch ----------------
extern "C" void kernel_launch(void* const* d_in, const int* in_sizes, int n_in,
                              void* d_out, int out_size) {
    const float* query     = (const float*)d_in[0];
    const float* value     = (const float*)d_in[1];
    const float* prev_attn = (const float*)d_in[2];
    const float* conv_w    = (const float*)d_in[3];
    const float* conv_b    = (const float*)d_in[4];
    const float* w_loc     = (const float*)d_in[5];
    const float* w_q       = (const float*)d_in[6];
    const float* w_v       = (const float*)d_in[7];
    const float* bias      = (const float*)d_in[8];
    const float* w_score   = (const float*)d_in[9];
    const float* b_score   = (const float*)d_in[10];
    const float* w_out     = (const float*)d_in[11];
    const float* b_out     = (const float*)d_in[12];
    float* out = (float*)d_out;

    (void)in_sizes; (void)n_in;

    cudaFuncSetAttribute(gemm_score_kernel,
                         cudaFuncAttributeMaxDynamicSharedMemorySize, SMEM_TOTAL_GEMM);

    prep_kernel<<< PREP_BLOCKS, 256 >>>(value, prev_attn, conv_w, conv_b,
                                        w_v, w_loc, query, w_q, bias);
    gemm_score_kernel<<< dim3(DIM_/BN, M_/BM), 128, SMEM_TOTAL_GEMM >>>(w_score);

    int write_attn = (out_size >= B_*H_ + M_) ? 1 : 0;   // output first, then attn
    normalize_kernel<<< B_, 256 >>>(b_score, out + B_*H_, write_attn);
    context_kernel<<< dim3(H_/512, B_, VLEN_/256), 256 >>>();
    output_kernel<<< dim3(H_/8, B_), 256 >>>(w_out, b_out, query, out);
}

// round 15
// speedup vs baseline: 1.4690x; 1.0761x over previous
#include <cuda_runtime.h>
#include <cuda_bf16.h>
#include <cstdint>

#define B_    32
#define VLEN_ 2048
#define H_    1024
#define DIM_  1024
#define C_    32
#define KC    1088              // 1024 (value) + 32 (conv feat) + 32 zero pad
#define M_    (B_*VLEN_)        // 65536

// ---------------- scratch (device globals: no runtime allocation) ----------------
__device__ __nv_bfloat16 g_valcat[(size_t)M_*KC];    // [65536][1088] bf16  (~142 MB)
__device__ __nv_bfloat16 g_wcat[(size_t)DIM_*KC];    // [1024][1088] bf16
__device__ float g_qbias[B_*DIM_];                   // qp[b,d] + bias[d]
__device__ float g_score[M_];
__device__ float g_attn[M_];
__device__ float g_context[B_*H_];

__device__ __forceinline__ uint32_t smem_u32(const void* p){
    return (uint32_t)__cvta_generic_to_shared(p);
}

#define MBARRIER_INIT(mbar, cnt) \
    asm volatile("mbarrier.init.shared.b64 [%0], %1;" :: "r"((uint32_t)(mbar)), "r"((uint32_t)(cnt)) : "memory")

#define MBARRIER_ARRIVE(mbar) \
    asm volatile("mbarrier.arrive.shared.b64 _, [%0];" :: "r"((uint32_t)(mbar)) : "memory")

#define MBARRIER_WAIT_PARITY(mbar_smem_addr, phase_parity) do { \
    uint32_t _mbar = (uint32_t)(mbar_smem_addr); \
    uint32_t _parity = (uint32_t)(phase_parity); \
    uint32_t _done; \
    asm volatile("{\n\t.reg .pred p;\n\t" \
        "mbarrier.try_wait.parity.acquire.cta.shared::cta.b64 p, [%1], %2;\n\t" \
        "selp.b32 %0, 1, 0, p;\n\t}" \
        : "=r"(_done) : "r"(_mbar), "r"(_parity) : "memory"); \
    if (!_done) { \
        asm volatile("{\n\t.reg .pred P1;\n\t" \
            "WAIT_LOOP_%=:\n\t" \
            "mbarrier.try_wait.parity.acquire.cta.shared::cta.b64 P1, [%0], %1, 0x989680;\n\t" \
            "@P1 bra.uni WAIT_DONE_%=;\n\t" \
            "bra.uni WAIT_LOOP_%=;\n\t" \
            "WAIT_DONE_%=:\n\t}" \
            :: "r"(_mbar), "r"(_parity) : "memory"); \
    } \
} while(0)

__device__ __forceinline__ float tanh_fast(float x){
    float r;
    asm("tanh.approx.f32 %0, %1;" : "=f"(r) : "f"(x));
    return r;
}

// ======== fused prep: valcat + wcat + qbias in ONE launch (blockIdx ranges) ========
#define VC_BLOCKS ((M_*(KC/8))/256)      // 34816
#define WC_BLOCKS ((DIM_*(KC/8))/256)    // 544
#define QB_BLOCKS ((DIM_/8)*B_)          // 4096
#define PREP_BLOCKS (VC_BLOCKS + WC_BLOCKS + QB_BLOCKS)

__global__ void prep_kernel(const float* __restrict__ value,
                            const float* __restrict__ prev_attn,
                            const float* __restrict__ conv_w,
                            const float* __restrict__ conv_b,
                            const float* __restrict__ w_v,
                            const float* __restrict__ w_loc,
                            const float* __restrict__ query,
                            const float* __restrict__ w_q,
                            const float* __restrict__ bias) {
    const int bid = blockIdx.x;
    const int CHUNKS = KC/8;                            // 136
    if (bid < VC_BLOCKS) {
        // ---- A matrix = [value(bf16) | conv_feat | 0]; also zeroes g_score ----
        int t = bid*256 + threadIdx.x;
        if (t < M_) g_score[t] = 0.f;
        int bv = t / CHUNKS, chunk = t % CHUNKS;
        __align__(16) __nv_bfloat16 o[8];
        if (chunk < 128) {
            const float4* s = reinterpret_cast<const float4*>(value + (size_t)bv*H_ + chunk*8);
            float4 x = s[0], y = s[1];
            o[0]=__float2bfloat16(x.x); o[1]=__float2bfloat16(x.y);
            o[2]=__float2bfloat16(x.z); o[3]=__float2bfloat16(x.w);
            o[4]=__float2bfloat16(y.x); o[5]=__float2bfloat16(y.y);
            o[6]=__float2bfloat16(y.z); o[7]=__float2bfloat16(y.w);
        } else if (chunk < 132) {
            int b = bv >> 11, v = bv & 2047;
            float pm = (v > 0)        ? prev_attn[b*VLEN_ + v - 1] : 0.f;
            float pc =                  prev_attn[b*VLEN_ + v];
            float pp = (v < VLEN_-1)  ? prev_attn[b*VLEN_ + v + 1] : 0.f;
            int c0 = (chunk-128)*8;
            #pragma unroll
            for (int j = 0; j < 8; j++) {
                int c = c0 + j;
                float cf = conv_w[c*3+0]*pm + conv_w[c*3+1]*pc + conv_w[c*3+2]*pp + conv_b[c];
                o[j] = __float2bfloat16(cf);
            }
        } else {
            #pragma unroll
            for (int j = 0; j < 8; j++) o[j] = __float2bfloat16(0.f);
        }
        *reinterpret_cast<uint4*>(g_valcat + (size_t)bv*KC + chunk*8) = *reinterpret_cast<uint4*>(o);
    } else if (bid < VC_BLOCKS + WC_BLOCKS) {
        // ---- B matrix = [w_v | w_loc | 0] ----
        int t = (bid - VC_BLOCKS)*256 + threadIdx.x;
        int d = t / CHUNKS, chunk = t % CHUNKS;
        __align__(16) __nv_bfloat16 o[8];
        if (chunk < 128) {
            const float* s = w_v + (size_t)d*H_ + chunk*8;
            #pragma unroll
            for (int j = 0; j < 8; j++) o[j] = __float2bfloat16(s[j]);
        } else if (chunk < 132) {
            const float* s = w_loc + (size_t)d*C_ + (chunk-128)*8;
            #pragma unroll
            for (int j = 0; j < 8; j++) o[j] = __float2bfloat16(s[j]);
        } else {
            #pragma unroll
            for (int j = 0; j < 8; j++) o[j] = __float2bfloat16(0.f);
        }
        *reinterpret_cast<uint4*>(g_wcat + (size_t)d*KC + chunk*8) = *reinterpret_cast<uint4*>(o);
    } else {
        // ---- qbias[b,d] = query[b].w_q[d] + bias[d] (fp32 exact) ----
        int blk = bid - VC_BLOCKS - WC_BLOCKS;      // 0..4095
        int warp = threadIdx.x >> 5, lane = threadIdx.x & 31;
        int b = blk >> 7;                           // /128
        int d = (blk & 127)*8 + warp;
        const float* q = query + b*H_;
        const float* w = w_q + (size_t)d*H_;
        float acc = 0.f;
        for (int h = lane; h < H_; h += 32) acc += q[h]*w[h];
        #pragma unroll
        for (int o = 16; o; o >>= 1) acc += __shfl_xor_sync(0xffffffffu, acc, o);
        if (!lane) g_qbias[b*DIM_ + d] = acc + bias[d];
    }
}

// ---------------- fused GEMM + tanh + score reduction (HMMA path) ----------------
// BM=128, BN=128; 4 warps (2x2), warp tile 64x64; KTILE=64, STG=3.
// mbarrier producer/consumer pipeline, no per-stage __syncthreads.
// empty[] barriers: count=4, ONE elected arrive per warp (ldmatrix.sync is
// warp-collective, so lane 0's arrive follows the whole warp's reads).
#define BM 128
#define BN 128
#define KTILE 64
#define NSTG  (KC/KTILE)   // 17
#define STG 3
#define KPAD 72            // 64 + 8 pad (144B rows -> conflict-free ldmatrix)

#define A_STG_ELEMS (BM*KPAD)            // 9216
#define B_STG_ELEMS (BN*KPAD)            // 9216
#define SM_A_OFF 0
#define SM_B_OFF (STG*A_STG_ELEMS*2)                    // 55296
#define SM_QB_OFF (SM_B_OFF + STG*B_STG_ELEMS*2)        // 110592
#define SM_WS_OFF (SM_QB_OFF + BN*4)
#define SM_MBAR_OFF (SM_WS_OFF + BN*4)                  // 6 x 8B mbarriers
#define SMEM_TOTAL_GEMM (SM_MBAR_OFF + 64)              // 111680

__device__ __forceinline__ void mma16816(float* c, const uint32_t* a, uint32_t b0, uint32_t b1) {
    asm("mma.sync.aligned.m16n8k16.row.col.f32.bf16.bf16.f32 "
        "{%0,%1,%2,%3}, {%4,%5,%6,%7}, {%8,%9}, {%0,%1,%2,%3};"
        : "+f"(c[0]), "+f"(c[1]), "+f"(c[2]), "+f"(c[3])
        : "r"(a[0]), "r"(a[1]), "r"(a[2]), "r"(a[3]), "r"(b0), "r"(b1));
}

__global__ __launch_bounds__(128, 2)
void gemm_score_kernel(const float* __restrict__ w_score) {
    extern __shared__ __align__(16) char sm[];
    __nv_bfloat16* As = reinterpret_cast<__nv_bfloat16*>(sm + SM_A_OFF);  // [STG][BM][KPAD]
    __nv_bfloat16* Bs = reinterpret_cast<__nv_bfloat16*>(sm + SM_B_OFF);  // [STG][BN][KPAD]
    float* qb_s = reinterpret_cast<float*>(sm + SM_QB_OFF);
    float* ws_s = reinterpret_cast<float*>(sm + SM_WS_OFF);
    const uint32_t mb_full  = smem_u32(sm + SM_MBAR_OFF);        // +8*slot
    const uint32_t mb_empty = mb_full + 24;                      // +8*slot

    const int t = threadIdx.x;         // 0..127
    const int warp = t >> 5, lane = t & 31;
    const int bn0 = blockIdx.x * BN;   // x fastest -> n-CTAs of one m-block co-resident
    const int bm0 = blockIdx.y * BM;
    const int batch = bm0 >> 11;       // 2048 rows per batch; BM | 2048

    qb_s[t] = g_qbias[batch*DIM_ + bn0 + t];       // t covers 0..127 = BN
    ws_s[t] = w_score[bn0 + t];

    if (t == 0) {
        #pragma unroll
        for (int i = 0; i < STG; i++) {
            MBARRIER_INIT(mb_full  + 8*i, 128);
            MBARRIER_INIT(mb_empty + 8*i, 4);      // one arrive per warp
        }
    }
    __syncthreads();   // qb_s/ws_s visible; mbarriers initialized before any arrive

    // stage loader: 128 rows x 8 chunks(16B) per matrix; 128 thr -> 8+8 chunks each
    const int lrow = t >> 3;      // 0..15
    const int lch  = t & 7;       // 16B chunk within 128B row
    const __nv_bfloat16* Ag = g_valcat + (size_t)bm0*KC + lch*8;
    const __nv_bfloat16* Bg = g_wcat   + (size_t)bn0*KC + lch*8;

    const int wm = (warp >> 1) * 64;   // 2 warps along M
    const int wn = (warp & 1) * 64;    // 2 warps along N
    const int g = lane >> 3, idx = lane & 7;
    const int a_row0 = wm + idx + 8*(g & 1);      // + mi*16
    const int a_col0 = 8*(g >> 1);                // + kb
    const int b_row0 = wn + idx + 8*(g >> 1);     // + ni*16
    const int b_col0 = 8*(g & 1);                 // + kb

    float acc[4][8][4];                // 128 regs
    #pragma unroll
    for (int i = 0; i < 4; i++)
        #pragma unroll
        for (int j = 0; j < 8; j++)
            #pragma unroll
            for (int k = 0; k < 4; k++) acc[i][j][k] = 0.f;

    auto load_stage = [&](int s) {
        int slot = s % STG;
        int k0 = s * KTILE;
        __nv_bfloat16* Ad = As + slot*A_STG_ELEMS;
        __nv_bfloat16* Bd = Bs + slot*B_STG_ELEMS;
        #pragma unroll
        for (int i = 0; i < 8; i++) {
            int r = lrow + i*16;
            uint32_t d = smem_u32(Ad + r*KPAD + lch*8);
            asm volatile("cp.async.cg.shared.global [%0], [%1], 16;\n"
                         :: "r"(d), "l"(Ag + (size_t)r*KC + k0));
            uint32_t db = smem_u32(Bd + r*KPAD + lch*8);
            asm volatile("cp.async.cg.shared.global [%0], [%1], 16;\n"
                         :: "r"(db), "l"(Bg + (size_t)r*KC + k0));
        }
        // this thread arrives on full[slot] when ALL its prior cp.asyncs land
        asm volatile("cp.async.mbarrier.arrive.noinc.shared::cta.b64 [%0];\n"
                     :: "r"(mb_full + 8*slot) : "memory");
    };

    // load one kk-half's fragments (8 ldmatrix.x4); kb in {0,16,32,48}
    auto ldsm_half = [&](int s, int kb, uint32_t a[4][4], uint32_t bf[4][4]) {
        const __nv_bfloat16* Asl = As + (s % STG)*A_STG_ELEMS;
        const __nv_bfloat16* Bsl = Bs + (s % STG)*B_STG_ELEMS;
        #pragma unroll
        for (int mi = 0; mi < 4; mi++) {
            uint32_t addr = smem_u32(Asl + (a_row0 + mi*16)*KPAD + a_col0 + kb);
            asm volatile("ldmatrix.sync.aligned.m8n8.x4.shared.b16 {%0,%1,%2,%3}, [%4];"
                         : "=r"(a[mi][0]), "=r"(a[mi][1]), "=r"(a[mi][2]), "=r"(a[mi][3])
                         : "r"(addr));
        }
        #pragma unroll
        for (int ni = 0; ni < 4; ni++) {
            uint32_t addr = smem_u32(Bsl + (b_row0 + ni*16)*KPAD + b_col0 + kb);
            asm volatile("ldmatrix.sync.aligned.m8n8.x4.shared.b16 {%0,%1,%2,%3}, [%4];"
                         : "=r"(bf[ni][0]), "=r"(bf[ni][1]), "=r"(bf[ni][2]), "=r"(bf[ni][3])
                         : "r"(addr));
        }
    };

    auto mma_half = [&](uint32_t a[4][4], uint32_t bf[4][4]) {
        #pragma unroll
        for (int mi = 0; mi < 4; mi++)
            #pragma unroll
            for (int ni = 0; ni < 4; ni++) {
                mma16816(acc[mi][ni*2+0], a[mi], bf[ni][0], bf[ni][1]);
                mma16816(acc[mi][ni*2+1], a[mi], bf[ni][2], bf[ni][3]);
            }
    };

    uint32_t a0[4][4], b0[4][4], a1[4][4], b1[4][4];

    // prologue: fill all 3 slots; wait stage 0 (full[0] phase 0)
    load_stage(0); load_stage(1); load_stage(2);
    MBARRIER_WAIT_PARITY(mb_full + 0, 0);
    ldsm_half(0, 0, a0, b0);

    for (int s = 0; s < NSTG; ++s) {
        int slot = s % STG;
        // 4 kk-halves of ping-pong
        ldsm_half(s, 16, a1, b1);  mma_half(a0, b0);
        ldsm_half(s, 32, a0, b0);  mma_half(a1, b1);
        ldsm_half(s, 48, a1, b1);
        if (lane == 0) MBARRIER_ARRIVE(mb_empty + 8*slot);  // warp's last read of slot s
        mma_half(a0, b0);
        if (s + 1 < NSTG) {
            MBARRIER_WAIT_PARITY(mb_full + 8*((s+1)%STG), ((s+1)/STG)&1);
            ldsm_half(s + 1, 0, a0, b0);
        }
        mma_half(a1, b1);
        if (s + 3 < NSTG) {
            // slot s%3 reused by stage s+3: wait consumers of round s/3 (acquire)
            MBARRIER_WAIT_PARITY(mb_empty + 8*slot, (s/STG)&1);
            load_stage(s + 3);
        }
    }

    // epilogue: tanh + weighted reduce over this CTA's 128 d-columns
    #pragma unroll
    for (int mi = 0; mi < 4; mi++) {
        float s0 = 0.f, s1 = 0.f;   // rows (lane>>2) and (lane>>2)+8
        #pragma unroll
        for (int j = 0; j < 8; j++) {
            int nc = wn + j*8 + 2*(lane & 3);
            float qb0 = qb_s[nc], qb1 = qb_s[nc+1];
            float w0 = ws_s[nc],  w1 = ws_s[nc+1];
            s0 += tanh_fast(acc[mi][j][0] + qb0)*w0 + tanh_fast(acc[mi][j][1] + qb1)*w1;
            s1 += tanh_fast(acc[mi][j][2] + qb0)*w0 + tanh_fast(acc[mi][j][3] + qb1)*w1;
        }
        s0 += __shfl_xor_sync(0xffffffffu, s0, 1);
        s0 += __shfl_xor_sync(0xffffffffu, s0, 2);
        s1 += __shfl_xor_sync(0xffffffffu, s1, 1);
        s1 += __shfl_xor_sync(0xffffffffu, s1, 2);
        if ((lane & 3) == 0) {
            int m0 = bm0 + wm + mi*16 + (lane >> 2);
            atomicAdd(&g_score[m0],     s0);
            atomicAdd(&g_score[m0 + 8], s1);
        }
    }
}

// ---------------- sigmoid + normalize -> attn (also zero context) ----------------
__global__ void normalize_kernel(const float* __restrict__ b_score, float* __restrict__ attn_out,
                                 int write_attn) {
    int b = blockIdx.x, t = threadIdx.x;     // 256 threads, 2048 elems
    __shared__ float red[256];
    for (int h = t; h < H_; h += 256) g_context[b*H_ + h] = 0.f;
    float bs = b_score[0];
    float sv[8];
    float local = 0.f;
    #pragma unroll
    for (int i = 0; i < 8; i++) {
        float x = g_score[b*VLEN_ + t + i*256] + bs;
        float s = 1.f / (1.f + __expf(-x));
        sv[i] = s; local += s;
    }
    red[t] = local; __syncthreads();
    #pragma unroll
    for (int o = 128; o; o >>= 1) { if (t < o) red[t] += red[t+o]; __syncthreads(); }
    float inv = 1.f / red[0];
    #pragma unroll
    for (int i = 0; i < 8; i++) {
        float a = sv[i] * inv;
        g_attn[b*VLEN_ + t + i*256] = a;
        if (write_attn) attn_out[b*VLEN_ + t + i*256] = a;
    }
}

// ------- context[b,h] = sum_v attn[b,v]*value[b,v,h]  (bf16x2 from g_valcat) -------
__global__ void context_kernel() {
    int hc = blockIdx.x, b = blockIdx.y, vs = blockIdx.z;   // (2, B, 8)
    int h2 = hc*256 + threadIdx.x;       // bf16x2 index; h = 2*h2
    __shared__ float a_s[256];
    a_s[threadIdx.x] = g_attn[b*VLEN_ + vs*256 + threadIdx.x];
    __syncthreads();
    const uint32_t* vp = reinterpret_cast<const uint32_t*>(
        g_valcat + ((size_t)b*VLEN_ + vs*256)*KC) + h2;
    float acc0 = 0.f, acc1 = 0.f;
    #pragma unroll 8
    for (int v = 0; v < 256; v++) {
        uint32_t u = vp[(size_t)v*(KC/2)];
        __nv_bfloat162 p = *reinterpret_cast<__nv_bfloat162*>(&u);
        float av = a_s[v];
        acc0 += av * __bfloat162float(p.x);
        acc1 += av * __bfloat162float(p.y);
    }
    atomicAdd(&g_context[b*H_ + 2*h2],     acc0);
    atomicAdd(&g_context[b*H_ + 2*h2 + 1], acc1);
}

// ---------------- output[b,h] = w_out[h] . [context | query] + b_out[h] ----------------
__global__ void output_kernel(const float* __restrict__ w_out, const float* __restrict__ b_out,
                              const float* __restrict__ query, float* __restrict__ out) {
    int b = blockIdx.y;
    int warp = threadIdx.x >> 5, lane = threadIdx.x & 31;
    int h = blockIdx.x*8 + warp;
    const float* wr = w_out + (size_t)h*(2*H_);
    const float* ctx = g_context + b*H_;
    const float* q = query + b*H_;
    float acc = 0.f;
    for (int k = lane; k < H_; k += 32) acc += wr[k]*ctx[k];
    for (int k = lane; k < H_; k += 32) acc += wr[H_+k]*q[k];
    #pragma unroll
    for (int o = 16; o; o >>= 1) acc += __shfl_xor_sync(0xffffffffu, acc, o);
    if (!lane) out[b*H_ + h] = acc + b_out[h];
}

// ---------------- launch ----------------
extern "C" void kernel_launch(void* const* d_in, const int* in_sizes, int n_in,
                              void* d_out, int out_size) {
    const float* query     = (const float*)d_in[0];
    const float* value     = (const float*)d_in[1];
    const float* prev_attn = (const float*)d_in[2];
    const float* conv_w    = (const float*)d_in[3];
    const float* conv_b    = (const float*)d_in[4];
    const float* w_loc     = (const float*)d_in[5];
    const float* w_q       = (const float*)d_in[6];
    const float* w_v       = (const float*)d_in[7];
    const float* bias      = (const float*)d_in[8];
    const float* w_score   = (const float*)d_in[9];
    const float* b_score   = (const float*)d_in[10];
    const float* w_out     = (const float*)d_in[11];
    const float* b_out     = (const float*)d_in[12];
    float* out = (float*)d_out;

    (void)in_sizes; (void)n_in;

    cudaFuncSetAttribute(gemm_score_kernel,
                         cudaFuncAttributeMaxDynamicSharedMemorySize, SMEM_TOTAL_GEMM);

    prep_kernel<<< PREP_BLOCKS, 256 >>>(value, prev_attn, conv_w, conv_b,
                                        w_v, w_loc, query, w_q, bias);
    gemm_score_kernel<<< dim3(DIM_/BN, M_/BM), 128, SMEM_TOTAL_GEMM >>>(w_score);

    int write_attn = (out_size >= B_*H_ + M_) ? 1 : 0;   // output first, then attn
    normalize_kernel<<< B_, 256 >>>(b_score, out + B_*H_, write_attn);
    context_kernel<<< dim3(H_/512, B_, VLEN_/256), 256 >>>();
    output_kernel<<< dim3(H_/8, B_), 256 >>>(w_out, b_out, query, out);
}